// round 15
// baseline (speedup 1.0000x reference)
#include <cuda_runtime.h>
#include <cuda_bf16.h>
#include <math.h>
#include <stdint.h>

// Problem constants
#define B_      4
#define S_      2048
#define D_      1024
#define H_      16
#define HD_     64
#define L_      6
#define SEQDIM_ 128
#define ROWS_   (B_ * S_)   // 8192

#define WT_PROJ_ELEMS (D_ * SEQDIM_)
#define WT_MAT_ELEMS  (D_ * D_)
#define WT_ELEMS      (WT_PROJ_ELEMS + 24 * WT_MAT_ELEMS)

// ---------------------------------------------------------------------------
// Device scratch
// ---------------------------------------------------------------------------
__device__ float g_x [ROWS_ * D_];
__device__ float g_t [ROWS_ * D_];
__device__ float g_op[2 * ROWS_ * D_];          // split-K attention partials
__device__ float2 g_ml[2 * B_ * H_ * S_];       // (m, l) per half/row
__device__ __nv_bfloat16 g_ah[ROWS_ * D_];
__device__ __nv_bfloat16 g_al[ROWS_ * D_];
__device__ __nv_bfloat16 g_wth[WT_ELEMS];
__device__ __nv_bfloat16 g_wtl[WT_ELEMS];
__device__ __nv_bfloat16 g_qh[ROWS_ * D_];
__device__ __nv_bfloat16 g_ql[ROWS_ * D_];
__device__ __nv_bfloat16 g_kh[ROWS_ * D_];
__device__ __nv_bfloat16 g_kl[ROWS_ * D_];
__device__ __nv_bfloat16 g_vth[ROWS_ * D_];     // [bh][64][S]
__device__ __nv_bfloat16 g_vtl[ROWS_ * D_];

// ---------------------------------------------------------------------------
// Helpers
// ---------------------------------------------------------------------------
__device__ __forceinline__ uint32_t smem_u32(const void* p) {
    uint32_t a;
    asm("{ .reg .u64 t; cvta.to.shared.u64 t, %1; cvt.u32.u64 %0, t; }"
        : "=r"(a) : "l"(p));
    return a;
}

__device__ __forceinline__ void ldm_x4(uint32_t* r, uint32_t addr) {
    asm("ldmatrix.sync.aligned.m8n8.x4.shared.b16 {%0,%1,%2,%3}, [%4];"
        : "=r"(r[0]), "=r"(r[1]), "=r"(r[2]), "=r"(r[3]) : "r"(addr));
}

__device__ __forceinline__ void mma16816(float* c, const uint32_t* a,
                                         uint32_t b0, uint32_t b1) {
    asm("mma.sync.aligned.m16n8k16.row.col.f32.bf16.bf16.f32 "
        "{%0,%1,%2,%3}, {%4,%5,%6,%7}, {%8,%9}, {%0,%1,%2,%3};"
        : "+f"(c[0]), "+f"(c[1]), "+f"(c[2]), "+f"(c[3])
        : "r"(a[0]), "r"(a[1]), "r"(a[2]), "r"(a[3]), "r"(b0), "r"(b1));
}

__device__ __forceinline__ uint32_t pk_bf16(float lo, float hi) {
    uint32_t r;
    asm("cvt.rn.bf16x2.f32 %0, %1, %2;" : "=r"(r) : "f"(hi), "f"(lo));
    return r;
}

__device__ __forceinline__ void split2(float c0, float c1, uint32_t& hw, uint32_t& lw) {
    __nv_bfloat16 h0 = __float2bfloat16(c0);
    __nv_bfloat16 h1 = __float2bfloat16(c1);
    __nv_bfloat162 hp; hp.x = h0; hp.y = h1;
    hw = *(uint32_t*)&hp;
    lw = pk_bf16(c0 - __bfloat162float(h0), c1 - __bfloat162float(h1));
}

#define CP_ASYNC16(dst, src) \
    asm volatile("cp.async.cg.shared.global [%0], [%1], 16;" :: "r"(dst), "l"(src))
#define CP_COMMIT() asm volatile("cp.async.commit_group;" ::: "memory")
#define CP_WAIT(n)  asm volatile("cp.async.wait_group %0;" :: "n"(n) : "memory")

// ---------------------------------------------------------------------------
// Unified prep: z<24 layer weight transpose+split; z==24 proj_w; z>=25 gather
// ---------------------------------------------------------------------------
__global__ void prep_all(const float* __restrict__ qw, const float* __restrict__ kw,
                         const float* __restrict__ vw, const float* __restrict__ ow,
                         const float* __restrict__ pw,
                         const int* __restrict__ seq, const float* __restrict__ emb,
                         __nv_bfloat16* __restrict__ th,
                         __nv_bfloat16* __restrict__ tl,
                         __nv_bfloat16* __restrict__ xh,
                         __nv_bfloat16* __restrict__ xl) {
    int z = blockIdx.z;
    if (z >= 25) {
        int tid = threadIdx.y * 32 + threadIdx.x;
        int i = (((z - 25) * 1024 + blockIdx.y * 32 + blockIdx.x) << 8) + tid;
        if (i >= ROWS_ * SEQDIM_ / 2) return;
        int row = i >> 6;
        int c2  = (i & 63) * 2;
        const float* e = emb + seq[row] * SEQDIM_ + c2;
        uint32_t hw, lw;
        split2(e[0], e[1], hw, lw);
        ((uint32_t*)xh)[i] = hw;
        ((uint32_t*)xl)[i] = lw;
        return;
    }
    __shared__ float t[32][33];
    const float* W;
    size_t dof;
    int K;
    if (z < 24) {
        int l = z >> 2, m = z & 3;
        W = (m == 0 ? qw : m == 1 ? kw : m == 2 ? vw : ow) + (size_t)l * D_ * D_;
        dof = WT_PROJ_ELEMS + (size_t)z * WT_MAT_ELEMS;
        K = D_;
    } else {
        if (blockIdx.y >= SEQDIM_ / 32) return;
        W = pw;
        dof = 0;
        K = SEQDIM_;
    }
    int bx = blockIdx.x * 32;
    int by = blockIdx.y * 32;
    #pragma unroll
    for (int i = 0; i < 32; i += 8)
        t[threadIdx.y + i][threadIdx.x] =
            W[(size_t)(by + threadIdx.y + i) * D_ + bx + threadIdx.x];
    __syncthreads();
    #pragma unroll
    for (int i = 0; i < 32; i += 8) {
        float v = t[threadIdx.x][threadIdx.y + i];
        int n = bx + threadIdx.y + i;
        int k = by + threadIdx.x;
        __nv_bfloat16 h = __float2bfloat16(v);
        th[dof + (size_t)n * K + k] = h;
        tl[dof + (size_t)n * K + k] = __float2bfloat16(v - __bfloat162float(h));
    }
}

// ---------------------------------------------------------------------------
// GEMM core (unchanged from R13)
// ---------------------------------------------------------------------------
#define TILEB  10240
#define CHUNKB (4 * TILEB)
#define GEMM_SMEM (2 * CHUNKB)

template <typename EPI>
__device__ __forceinline__
void gemm_core(const __nv_bfloat16* s0, const __nv_bfloat16* s1,
               const __nv_bfloat16* s2, const __nv_bfloat16* s3,
               int K, char* smem, EPI epilogue) {
    const uint32_t sb = smem_u32(smem);
    const int tid  = threadIdx.x;
    const int lane = tid & 31;
    const int wid  = tid >> 5;
    const int wm = wid & 1;
    const int wn = wid >> 1;

    const int nk = K >> 5;

    auto load_chunk = [&](int c, int stage) {
        const int k0 = c << 5;
        uint32_t buf = sb + stage * CHUNKB;
        #pragma unroll
        for (int i = 0; i < 2; i++) {
            int t = tid + i * 256;
            int row = t >> 2;
            int seg = t & 3;
            uint32_t dst = buf + row * 80 + seg * 16;
            size_t so = (size_t)row * K + k0 + seg * 8;
            CP_ASYNC16(dst,              (const char*)(s0 + so));
            CP_ASYNC16(dst + TILEB,      (const char*)(s1 + so));
            CP_ASYNC16(dst + 2 * TILEB,  (const char*)(s2 + so));
            CP_ASYNC16(dst + 3 * TILEB,  (const char*)(s3 + so));
        }
        CP_COMMIT();
    };

    float acc[4][4][4];
    #pragma unroll
    for (int mi = 0; mi < 4; mi++)
        #pragma unroll
        for (int nb = 0; nb < 4; nb++)
            #pragma unroll
            for (int j = 0; j < 4; j++) acc[mi][nb][j] = 0.f;

    const uint32_t a_off = (uint32_t)((wm * 64 + (lane & 15)) * 80 + (lane >> 4) * 16);
    const uint32_t b_off = (uint32_t)((wn * 32 + ((lane >> 4) & 1) * 8 + (lane & 7)) * 80
                                      + ((lane >> 3) & 1) * 16);

    load_chunk(0, 0);

    for (int c = 0; c < nk; c++) {
        CP_WAIT(0);
        __syncthreads();
        if (c + 1 < nk) load_chunk(c + 1, (c + 1) & 1);

        uint32_t buf = sb + (c & 1) * CHUNKB;
        #pragma unroll
        for (int s = 0; s < 2; s++) {
            uint32_t ah[4][4], al[4][4], wh[2][4], wl[2][4];
            #pragma unroll
            for (int g = 0; g < 4; g++)
                ldm_x4(ah[g], buf + a_off + (uint32_t)(g * 16 * 80 + s * 32));
            #pragma unroll
            for (int h = 0; h < 2; h++)
                ldm_x4(wh[h], buf + 2 * TILEB + b_off + (uint32_t)(h * 16 * 80 + s * 32));
            #pragma unroll
            for (int mi = 0; mi < 4; mi++)
                #pragma unroll
                for (int nb = 0; nb < 4; nb++) {
                    const int h = nb >> 1, j = nb & 1;
                    mma16816(acc[mi][nb], ah[mi], wh[h][2 * j], wh[h][2 * j + 1]);
                }
            #pragma unroll
            for (int h = 0; h < 2; h++)
                ldm_x4(wl[h], buf + 3 * TILEB + b_off + (uint32_t)(h * 16 * 80 + s * 32));
            #pragma unroll
            for (int mi = 0; mi < 4; mi++)
                #pragma unroll
                for (int nb = 0; nb < 4; nb++) {
                    const int h = nb >> 1, j = nb & 1;
                    mma16816(acc[mi][nb], ah[mi], wl[h][2 * j], wl[h][2 * j + 1]);
                }
            #pragma unroll
            for (int g = 0; g < 4; g++)
                ldm_x4(al[g], buf + TILEB + a_off + (uint32_t)(g * 16 * 80 + s * 32));
            #pragma unroll
            for (int mi = 0; mi < 4; mi++)
                #pragma unroll
                for (int nb = 0; nb < 4; nb++) {
                    const int h = nb >> 1, j = nb & 1;
                    mma16816(acc[mi][nb], al[mi], wh[h][2 * j], wh[h][2 * j + 1]);
                }
        }
    }
    __syncthreads();

    epilogue(acc, wm, wn, lane);
}

// ---------------------------------------------------------------------------
// Generic GEMM + bias -> fp32 C (optionally also emit bf16 hi/lo split)
// ---------------------------------------------------------------------------
template <bool SPLIT>
__global__ __launch_bounds__(256, 2)
void gemm_mma(const __nv_bfloat16* __restrict__ Ah,
              const __nv_bfloat16* __restrict__ Al,
              const __nv_bfloat16* __restrict__ Wh,
              const __nv_bfloat16* __restrict__ Wl,
              const float* __restrict__ bias,
              float* __restrict__ C, int N, int K,
              __nv_bfloat16* __restrict__ oh, __nv_bfloat16* __restrict__ ol) {
    extern __shared__ char smem[];
    const int brow = blockIdx.y * 128;
    const int bcol = blockIdx.x * 128;
    gemm_core(Ah + (size_t)brow * K, Al + (size_t)brow * K,
              Wh + (size_t)bcol * K, Wl + (size_t)bcol * K, K, smem,
        [&](float acc[4][4][4], int wm, int wn, int lane) {
            #pragma unroll
            for (int mi = 0; mi < 4; mi++) {
                int row = brow + wm * 64 + mi * 16 + (lane >> 2);
                #pragma unroll
                for (int nb = 0; nb < 4; nb++) {
                    int col = bcol + wn * 32 + nb * 8 + (lane & 3) * 2;
                    float b0 = bias[col], b1 = bias[col + 1];
                    float c00 = acc[mi][nb][0] + b0, c01 = acc[mi][nb][1] + b1;
                    float c10 = acc[mi][nb][2] + b0, c11 = acc[mi][nb][3] + b1;
                    size_t i0 = (size_t)row * N + col;
                    size_t i1 = (size_t)(row + 8) * N + col;
                    *(float2*)(C + i0) = make_float2(c00, c01);
                    *(float2*)(C + i1) = make_float2(c10, c11);
                    if (SPLIT) {
                        uint32_t hw, lw;
                        split2(c00, c01, hw, lw);
                        *(uint32_t*)(oh + i0) = hw; *(uint32_t*)(ol + i0) = lw;
                        split2(c10, c11, hw, lw);
                        *(uint32_t*)(oh + i1) = hw; *(uint32_t*)(ol + i1) = lw;
                    }
                }
            }
        });
}

// ---------------------------------------------------------------------------
// Fused QKV GEMM (N=3072). V emitted transposed+split via smem staging.
// ---------------------------------------------------------------------------
__global__ __launch_bounds__(256, 2)
void gemm_qkv(const __nv_bfloat16* __restrict__ Ah,
              const __nv_bfloat16* __restrict__ Al,
              const __nv_bfloat16* __restrict__ Wh,
              const __nv_bfloat16* __restrict__ Wl,
              const float* __restrict__ qb, const float* __restrict__ kb,
              const float* __restrict__ vb, int lofs,
              __nv_bfloat16* __restrict__ qh, __nv_bfloat16* __restrict__ ql,
              __nv_bfloat16* __restrict__ kh, __nv_bfloat16* __restrict__ kl,
              __nv_bfloat16* __restrict__ vth, __nv_bfloat16* __restrict__ vtl) {
    extern __shared__ char smem[];
    const int K = D_;
    const int brow = blockIdx.y * 128;
    const int bcol = blockIdx.x * 128;
    const int mat = bcol >> 10;
    const int colb = bcol & 1023;
    const float* bias = (mat == 0 ? qb : mat == 1 ? kb : vb) + lofs;
    gemm_core(Ah + (size_t)brow * K, Al + (size_t)brow * K,
              Wh + (size_t)bcol * K, Wl + (size_t)bcol * K, K, smem,
        [&](float acc[4][4][4], int wm, int wn, int lane) {
            if (mat == 2) {
                float* trans = (float*)smem;
                #pragma unroll
                for (int mi = 0; mi < 4; mi++) {
                    int sl = wm * 64 + mi * 16 + (lane >> 2);
                    #pragma unroll
                    for (int nb = 0; nb < 4; nb++) {
                        int dl = wn * 32 + nb * 8 + (lane & 3) * 2;
                        float b0 = bias[colb + dl], b1 = bias[colb + dl + 1];
                        trans[dl * 132 + sl]           = acc[mi][nb][0] + b0;
                        trans[(dl + 1) * 132 + sl]     = acc[mi][nb][1] + b1;
                        trans[dl * 132 + sl + 8]       = acc[mi][nb][2] + b0;
                        trans[(dl + 1) * 132 + sl + 8] = acc[mi][nb][3] + b1;
                    }
                }
                __syncthreads();
                int bb = brow >> 11;
                int s0 = brow & (S_ - 1);
                #pragma unroll
                for (int i = 0; i < 32; i++) {
                    int idx = (int)threadIdx.x + i * 256;
                    int dl = idx >> 6;
                    int sp = idx & 63;
                    float2 v = *(float2*)&trans[dl * 132 + sp * 2];
                    int col = colb + dl;
                    int hh = col >> 6, dd = col & 63;
                    size_t o = ((size_t)(bb * H_ + hh) * HD_ + dd) * S_ + s0 + sp * 2;
                    uint32_t hw, lw;
                    split2(v.x, v.y, hw, lw);
                    *(uint32_t*)(vth + o) = hw;
                    *(uint32_t*)(vtl + o) = lw;
                }
            } else {
                #pragma unroll
                for (int mi = 0; mi < 4; mi++) {
                    int row = brow + wm * 64 + mi * 16 + (lane >> 2);
                    #pragma unroll
                    for (int nb = 0; nb < 4; nb++) {
                        int col = colb + wn * 32 + nb * 8 + (lane & 3) * 2;
                        float b0 = bias[col], b1 = bias[col + 1];
                        float c00 = acc[mi][nb][0] + b0, c01 = acc[mi][nb][1] + b1;
                        float c10 = acc[mi][nb][2] + b0, c11 = acc[mi][nb][3] + b1;
                        size_t i0 = (size_t)row * D_ + col;
                        size_t i1 = (size_t)(row + 8) * D_ + col;
                        __nv_bfloat16* hB = (mat == 0) ? qh : kh;
                        __nv_bfloat16* lB = (mat == 0) ? ql : kl;
                        if (mat == 0) { c00 *= 0.125f; c01 *= 0.125f; c10 *= 0.125f; c11 *= 0.125f; }
                        uint32_t hw, lw;
                        split2(c00, c01, hw, lw);
                        *(uint32_t*)(hB + i0) = hw; *(uint32_t*)(lB + i0) = lw;
                        split2(c10, c11, hw, lw);
                        *(uint32_t*)(hB + i1) = hw; *(uint32_t*)(lB + i1) = lw;
                    }
                }
            }
        });
}

// ---------------------------------------------------------------------------
// Split-K tensor-core flash attention. blockIdx.z = key half (0/1).
// Emits UNNORMALIZED partial O (fp32) + per-row (m, l). NKT=16 per half.
// ---------------------------------------------------------------------------
#define AST      36864
#define AKL      9216
#define AMASK    (2 * AST)
#define AQLO     (AMASK + 512)
#define ATT_SMEM (AQLO + 18432)        // 92672

__global__ __launch_bounds__(256, 2)
void attn_mma(const __nv_bfloat16* __restrict__ qh, const __nv_bfloat16* __restrict__ ql,
              const __nv_bfloat16* __restrict__ kh, const __nv_bfloat16* __restrict__ kl,
              const __nv_bfloat16* __restrict__ vth, const __nv_bfloat16* __restrict__ vtl,
              const int* __restrict__ mask,
              float* __restrict__ opart, float2* __restrict__ ml) {
    extern __shared__ char smem[];
    const uint32_t sb = smem_u32(smem);
    const int tid = threadIdx.x, wid = tid >> 5, lane = tid & 31;
    const int q0 = blockIdx.x * 128;
    const int bh = blockIdx.y;
    const int half = blockIdx.z;
    const int b = bh >> 4, h = bh & 15;
    const size_t rowbase = (size_t)b * S_;
    const int kbase = half << 10;           // 0 or 1024

    #pragma unroll
    for (int i = 0; i < 4; i++) {
        int t = tid + i * 256;
        int row = t >> 3, seg = t & 7;
        size_t so = (rowbase + q0 + row) * D_ + h * HD_ + seg * 8;
        CP_ASYNC16(sb + row * 144 + seg * 16,        (const char*)(qh + so));
        CP_ASYNC16(sb + AQLO + row * 144 + seg * 16, (const char*)(ql + so));
    }
    CP_COMMIT(); CP_WAIT(0);
    __syncthreads();

    uint32_t qhf[4][4];
    const uint32_t q_off = (uint32_t)((wid * 16 + (lane & 15)) * 144 + (lane >> 4) * 16);
    #pragma unroll
    for (int s = 0; s < 4; s++)
        ldm_x4(qhf[s], sb + q_off + s * 32);
    __syncthreads();

    auto load_kv = [&](int kt, int st) {
        uint32_t buf = sb + st * AST;
        int key0 = kbase + kt * 64;
        #pragma unroll
        for (int i = 0; i < 2; i++) {
            int t = tid + i * 256;
            int row = t >> 3, seg = t & 7;
            uint32_t dst = buf + row * 144 + seg * 16;
            size_t sk = (rowbase + key0 + row) * D_ + h * HD_ + seg * 8;
            CP_ASYNC16(dst,           (const char*)(kh + sk));
            CP_ASYNC16(dst + AKL,     (const char*)(kl + sk));
            size_t sv = ((size_t)bh * HD_ + row) * S_ + key0 + seg * 8;
            CP_ASYNC16(dst + 2 * AKL, (const char*)(vth + sv));
            CP_ASYNC16(dst + 3 * AKL, (const char*)(vtl + sv));
        }
        if (tid < 16)
            CP_ASYNC16(sb + AMASK + st * 256 + tid * 16,
                       (const char*)(mask + b * S_ + key0 + tid * 4));
        CP_COMMIT();
    };

    float oacc[8][4];
    #pragma unroll
    for (int nb = 0; nb < 8; nb++)
        #pragma unroll
        for (int j = 0; j < 4; j++) oacc[nb][j] = 0.f;
    float mrow0 = -1e30f, mrow1 = -1e30f, lrow0 = 0.f, lrow1 = 0.f;

    const uint32_t bfrag_off = (uint32_t)((((lane >> 4) & 1) * 8 + (lane & 7)) * 144
                                          + ((lane >> 3) & 1) * 16);

    const int NKT = 16;
    load_kv(0, 0);

    for (int kt = 0; kt < NKT; kt++) {
        CP_WAIT(0);
        __syncthreads();
        if (kt + 1 < NKT) load_kv(kt + 1, (kt + 1) & 1);

        uint32_t buf = sb + (kt & 1) * AST;

        float sacc[8][4];
        #pragma unroll
        for (int nb = 0; nb < 8; nb++)
            #pragma unroll
            for (int j = 0; j < 4; j++) sacc[nb][j] = 0.f;

        #pragma unroll
        for (int s = 0; s < 4; s++) {
            uint32_t khf[4][4], klf[4][4], qlf[4];
            #pragma unroll
            for (int g = 0; g < 4; g++)
                ldm_x4(khf[g], buf + bfrag_off + (uint32_t)(g * 16 * 144 + s * 32));
            #pragma unroll
            for (int g = 0; g < 4; g++)
                #pragma unroll
                for (int j = 0; j < 2; j++)
                    mma16816(sacc[g * 2 + j], qhf[s], khf[g][2 * j], khf[g][2 * j + 1]);
            #pragma unroll
            for (int g = 0; g < 4; g++)
                ldm_x4(klf[g], buf + AKL + bfrag_off + (uint32_t)(g * 16 * 144 + s * 32));
            #pragma unroll
            for (int g = 0; g < 4; g++)
                #pragma unroll
                for (int j = 0; j < 2; j++)
                    mma16816(sacc[g * 2 + j], qhf[s], klf[g][2 * j], klf[g][2 * j + 1]);
            ldm_x4(qlf, sb + AQLO + q_off + s * 32);
            #pragma unroll
            for (int g = 0; g < 4; g++)
                #pragma unroll
                for (int j = 0; j < 2; j++)
                    mma16816(sacc[g * 2 + j], qlf, khf[g][2 * j], khf[g][2 * j + 1]);
        }

        {
            const int* smk = (const int*)(smem + AMASK + (kt & 1) * 256);
            int cb = 2 * (lane & 3);
            #pragma unroll
            for (int nb = 0; nb < 8; nb++) {
                if (smk[nb * 8 + cb] == 0)     { sacc[nb][0] = -1e9f; sacc[nb][2] = -1e9f; }
                if (smk[nb * 8 + cb + 1] == 0) { sacc[nb][1] = -1e9f; sacc[nb][3] = -1e9f; }
            }
        }

        float mx0 = -1e30f, mx1 = -1e30f;
        #pragma unroll
        for (int nb = 0; nb < 8; nb++) {
            mx0 = fmaxf(mx0, fmaxf(sacc[nb][0], sacc[nb][1]));
            mx1 = fmaxf(mx1, fmaxf(sacc[nb][2], sacc[nb][3]));
        }
        mx0 = fmaxf(mx0, __shfl_xor_sync(0xffffffffu, mx0, 1));
        mx0 = fmaxf(mx0, __shfl_xor_sync(0xffffffffu, mx0, 2));
        mx1 = fmaxf(mx1, __shfl_xor_sync(0xffffffffu, mx1, 1));
        mx1 = fmaxf(mx1, __shfl_xor_sync(0xffffffffu, mx1, 2));
        float mn0 = fmaxf(mrow0, mx0), mn1 = fmaxf(mrow1, mx1);
        float corr0 = __expf(mrow0 - mn0), corr1 = __expf(mrow1 - mn1);
        float sum0 = 0.f, sum1 = 0.f;
        #pragma unroll
        for (int nb = 0; nb < 8; nb++) {
            sacc[nb][0] = __expf(sacc[nb][0] - mn0);
            sacc[nb][1] = __expf(sacc[nb][1] - mn0);
            sacc[nb][2] = __expf(sacc[nb][2] - mn1);
            sacc[nb][3] = __expf(sacc[nb][3] - mn1);
            sum0 += sacc[nb][0] + sacc[nb][1];
            sum1 += sacc[nb][2] + sacc[nb][3];
        }
        sum0 += __shfl_xor_sync(0xffffffffu, sum0, 1);
        sum0 += __shfl_xor_sync(0xffffffffu, sum0, 2);
        sum1 += __shfl_xor_sync(0xffffffffu, sum1, 1);
        sum1 += __shfl_xor_sync(0xffffffffu, sum1, 2);
        lrow0 = lrow0 * corr0 + sum0;
        lrow1 = lrow1 * corr1 + sum1;
        mrow0 = mn0; mrow1 = mn1;
        #pragma unroll
        for (int nb = 0; nb < 8; nb++) {
            oacc[nb][0] *= corr0; oacc[nb][1] *= corr0;
            oacc[nb][2] *= corr1; oacc[nb][3] *= corr1;
        }

        #pragma unroll
        for (int c = 0; c < 4; c++) {
            uint32_t pha[4], pla[4];
            #pragma unroll
            for (int half2 = 0; half2 < 2; half2++) {
                int nb = 2 * c + half2;
                __nv_bfloat16 b0 = __float2bfloat16(sacc[nb][0]);
                __nv_bfloat16 b1 = __float2bfloat16(sacc[nb][1]);
                __nv_bfloat16 b2 = __float2bfloat16(sacc[nb][2]);
                __nv_bfloat16 b3 = __float2bfloat16(sacc[nb][3]);
                __nv_bfloat162 t01; t01.x = b0; t01.y = b1;
                __nv_bfloat162 t23; t23.x = b2; t23.y = b3;
                pha[half2 * 2 + 0] = *(uint32_t*)&t01;
                pha[half2 * 2 + 1] = *(uint32_t*)&t23;
                pla[half2 * 2 + 0] = pk_bf16(sacc[nb][0] - __bfloat162float(b0),
                                             sacc[nb][1] - __bfloat162float(b1));
                pla[half2 * 2 + 1] = pk_bf16(sacc[nb][2] - __bfloat162float(b2),
                                             sacc[nb][3] - __bfloat162float(b3));
            }
            uint32_t vhf[4][4], vlf[4][4];
            #pragma unroll
            for (int g = 0; g < 4; g++)
                ldm_x4(vhf[g], buf + 2 * AKL + bfrag_off + (uint32_t)(g * 16 * 144 + c * 32));
            #pragma unroll
            for (int g = 0; g < 4; g++)
                #pragma unroll
                for (int j = 0; j < 2; j++)
                    mma16816(oacc[g * 2 + j], pha, vhf[g][2 * j], vhf[g][2 * j + 1]);
            #pragma unroll
            for (int g = 0; g < 4; g++)
                ldm_x4(vlf[g], buf + 3 * AKL + bfrag_off + (uint32_t)(g * 16 * 144 + c * 32));
            #pragma unroll
            for (int g = 0; g < 4; g++)
                #pragma unroll
                for (int j = 0; j < 2; j++)
                    mma16816(oacc[g * 2 + j], pha, vlf[g][2 * j], vlf[g][2 * j + 1]);
            #pragma unroll
            for (int g = 0; g < 4; g++)
                #pragma unroll
                for (int j = 0; j < 2; j++)
                    mma16816(oacc[g * 2 + j], pla, vhf[g][2 * j], vhf[g][2 * j + 1]);
        }
    }

    // Epilogue: unnormalized partial O + (m, l)
    float* op = opart + (size_t)half * ROWS_ * D_;
    int r0 = q0 + wid * 16 + (lane >> 2);
    #pragma unroll
    for (int nb = 0; nb < 8; nb++) {
        int col = h * HD_ + nb * 8 + 2 * (lane & 3);
        size_t i0 = (rowbase + r0) * D_ + col;
        size_t i1 = (rowbase + r0 + 8) * D_ + col;
        *(float2*)(op + i0) = make_float2(oacc[nb][0], oacc[nb][1]);
        *(float2*)(op + i1) = make_float2(oacc[nb][2], oacc[nb][3]);
    }
    if ((lane & 3) == 0) {
        size_t mlbase = ((size_t)half * B_ * H_ + bh) * S_;
        ml[mlbase + r0]     = make_float2(mrow0, lrow0);
        ml[mlbase + r0 + 8] = make_float2(mrow1, lrow1);
    }
}

// ---------------------------------------------------------------------------
// Split-K combine: merge 2 halves, normalize, emit bf16 hi/lo split
// ---------------------------------------------------------------------------
__global__ __launch_bounds__(256)
void attn_combine(const float* __restrict__ opart, const float2* __restrict__ ml,
                  __nv_bfloat16* __restrict__ oh, __nv_bfloat16* __restrict__ ol) {
    int row = blockIdx.x;                 // 0..8191
    int b = row >> 11, s = row & (S_ - 1);
    int tid = threadIdx.x;
    const float* o0 = opart + (size_t)row * D_;
    const float* o1 = opart + (size_t)ROWS_ * D_ + (size_t)row * D_;
    #pragma unroll
    for (int i = 0; i < 2; i++) {
        int c2 = (tid + i * 256) * 2;     // even col
        int h  = c2 >> 6;
        size_t mlb = ((size_t)(b * H_ + h)) * S_ + s;
        float2 m1 = ml[mlb];
        float2 m2 = ml[(size_t)B_ * H_ * S_ + mlb];
        float m  = fmaxf(m1.x, m2.x);
        float w1 = __expf(m1.x - m), w2 = __expf(m2.x - m);
        float inv = 1.0f / (w1 * m1.y + w2 * m2.y);
        float2 a = *(const float2*)(o0 + c2);
        float2 c = *(const float2*)(o1 + c2);
        float v0 = (w1 * a.x + w2 * c.x) * inv;
        float v1 = (w1 * a.y + w2 * c.y) * inv;
        uint32_t hw, lw;
        split2(v0, v1, hw, lw);
        size_t o = (size_t)row * D_ + c2;
        *(uint32_t*)(oh + o) = hw;
        *(uint32_t*)(ol + o) = lw;
    }
}

// ---------------------------------------------------------------------------
// Fused residual add + LayerNorm (warp-shuffle reductions)
// ---------------------------------------------------------------------------
template <bool SPLIT>
__global__ __launch_bounds__(256)
void add_ln(const float* __restrict__ x, const float* __restrict__ y,
            const float* __restrict__ g, const float* __restrict__ bta,
            float* __restrict__ out,
            __nv_bfloat16* __restrict__ oh, __nv_bfloat16* __restrict__ ol) {
    __shared__ float red[16];
    int row = blockIdx.x, tid = threadIdx.x;
    int wid = tid >> 5, lane = tid & 31;
    const float* xr = x + (size_t)row * D_;
    const float* yr = y + (size_t)row * D_;

    float v[4];
    float sum = 0.f, sq = 0.f;
    #pragma unroll
    for (int i = 0; i < 4; i++) {
        int c = tid + i * 256;
        v[i] = xr[c] + yr[c];
        sum += v[i];
        sq  += v[i] * v[i];
    }
    #pragma unroll
    for (int off = 16; off; off >>= 1) {
        sum += __shfl_xor_sync(0xffffffffu, sum, off);
        sq  += __shfl_xor_sync(0xffffffffu, sq,  off);
    }
    if (lane == 0) { red[wid] = sum; red[8 + wid] = sq; }
    __syncthreads();
    float ts = red[lane & 7], tq = red[8 + (lane & 7)];
    #pragma unroll
    for (int off = 4; off; off >>= 1) {
        ts += __shfl_xor_sync(0xffffffffu, ts, off);
        tq += __shfl_xor_sync(0xffffffffu, tq, off);
    }
    ts = __shfl_sync(0xffffffffu, ts, 0);
    tq = __shfl_sync(0xffffffffu, tq, 0);
    float mu   = ts * (1.0f / 1024.0f);
    float var  = tq * (1.0f / 1024.0f) - mu * mu;
    float rstd = rsqrtf(var + 1e-5f);

    #pragma unroll
    for (int i = 0; i < 4; i++) {
        int c = tid + i * 256;
        float o = (v[i] - mu) * rstd * g[c] + bta[c];
        out[(size_t)row * D_ + c] = o;
        if (SPLIT) {
            __nv_bfloat16 h = __float2bfloat16(o);
            oh[(size_t)row * D_ + c] = h;
            ol[(size_t)row * D_ + c] = __float2bfloat16(o - __bfloat162float(h));
        }
    }
}

// ---------------------------------------------------------------------------
// Launch
// ---------------------------------------------------------------------------
extern "C" void kernel_launch(void* const* d_in, const int* in_sizes, int n_in,
                              void* d_out, int out_size) {
    const int*   seq    = (const int*)  d_in[0];
    const int*   mask   = (const int*)  d_in[1];
    const float* emb    = (const float*)d_in[2];
    const float* proj_w = (const float*)d_in[3];
    const float* proj_b = (const float*)d_in[4];
    const float* qw     = (const float*)d_in[5];
    const float* qb     = (const float*)d_in[6];
    const float* kw     = (const float*)d_in[7];
    const float* kb     = (const float*)d_in[8];
    const float* vw     = (const float*)d_in[9];
    const float* vb     = (const float*)d_in[10];
    const float* ow     = (const float*)d_in[11];
    const float* ob     = (const float*)d_in[12];
    const float* lng    = (const float*)d_in[13];
    const float* lnb    = (const float*)d_in[14];
    float* out = (float*)d_out;

    float *x, *t, *op;
    float2* mlp;
    __nv_bfloat16 *ah, *al, *wth, *wtl, *qhp, *qlp, *khp, *klp, *vthp, *vtlp;
    cudaGetSymbolAddress((void**)&x,    g_x);
    cudaGetSymbolAddress((void**)&t,    g_t);
    cudaGetSymbolAddress((void**)&op,   g_op);
    cudaGetSymbolAddress((void**)&mlp,  g_ml);
    cudaGetSymbolAddress((void**)&ah,   g_ah);
    cudaGetSymbolAddress((void**)&al,   g_al);
    cudaGetSymbolAddress((void**)&wth,  g_wth);
    cudaGetSymbolAddress((void**)&wtl,  g_wtl);
    cudaGetSymbolAddress((void**)&qhp,  g_qh);
    cudaGetSymbolAddress((void**)&qlp,  g_ql);
    cudaGetSymbolAddress((void**)&khp,  g_kh);
    cudaGetSymbolAddress((void**)&klp,  g_kl);
    cudaGetSymbolAddress((void**)&vthp, g_vth);
    cudaGetSymbolAddress((void**)&vtlp, g_vtl);

    cudaFuncSetAttribute(gemm_mma<false>, cudaFuncAttributeMaxDynamicSharedMemorySize, GEMM_SMEM);
    cudaFuncSetAttribute(gemm_mma<true>,  cudaFuncAttributeMaxDynamicSharedMemorySize, GEMM_SMEM);
    cudaFuncSetAttribute(gemm_qkv, cudaFuncAttributeMaxDynamicSharedMemorySize, GEMM_SMEM);
    cudaFuncSetAttribute(attn_mma, cudaFuncAttributeMaxDynamicSharedMemorySize, ATT_SMEM);

    prep_all<<<dim3(D_ / 32, D_ / 32, 27), dim3(32, 8)>>>(qw, kw, vw, ow, proj_w,
                                                          seq, emb, wth, wtl, qhp, qlp);
    dim3 gp(D_ / 128, ROWS_ / 128);
    gemm_mma<true><<<gp, 256, GEMM_SMEM>>>(qhp, qlp, wth, wtl, proj_b, x, D_, SEQDIM_, ah, al);

    dim3 gqkv(3 * D_ / 128, ROWS_ / 128);        // (24, 64)
    dim3 ga(S_ / 128, B_ * H_, 2);               // (16, 64, 2) split-K halves
    for (int l = 0; l < L_; l++) {
        size_t off = WT_PROJ_ELEMS + (size_t)(l * 4) * WT_MAT_ELEMS;
        const __nv_bfloat16* owh = wth + off + 3 * WT_MAT_ELEMS;
        const __nv_bfloat16* owl = wtl + off + 3 * WT_MAT_ELEMS;

        gemm_qkv<<<gqkv, 256, GEMM_SMEM>>>(ah, al, wth + off, wtl + off,
                                           qb, kb, vb, l * D_,
                                           qhp, qlp, khp, klp, vthp, vtlp);
        attn_mma<<<ga, 256, ATT_SMEM>>>(qhp, qlp, khp, klp, vthp, vtlp, mask, op, mlp);
        attn_combine<<<ROWS_, 256>>>(op, mlp, ah, al);
        gemm_mma<false><<<gp, 256, GEMM_SMEM>>>(ah, al, owh, owl, ob + l * D_, t, D_, D_,
                                                nullptr, nullptr);
        if (l == L_ - 1)
            add_ln<false><<<ROWS_, 256>>>(x, t, lng + l * D_, lnb + l * D_, out, nullptr, nullptr);
        else
            add_ln<true><<<ROWS_, 256>>>(x, t, lng + l * D_, lnb + l * D_, x, ah, al);
    }
}

// round 16
// speedup vs baseline: 1.0148x; 1.0148x over previous
#include <cuda_runtime.h>
#include <cuda_bf16.h>
#include <math.h>
#include <stdint.h>

// Problem constants
#define B_      4
#define S_      2048
#define D_      1024
#define H_      16
#define HD_     64
#define L_      6
#define SEQDIM_ 128
#define ROWS_   (B_ * S_)   // 8192

#define WT_PROJ_ELEMS (D_ * SEQDIM_)
#define WT_MAT_ELEMS  (D_ * D_)
#define WT_ELEMS      (WT_PROJ_ELEMS + 24 * WT_MAT_ELEMS)

// Q pre-scale: 1/sqrt(64) * log2(e)  (softmax runs in exp2 domain)
#define QSCALE  0.18033688f

// ---------------------------------------------------------------------------
// Device scratch
// ---------------------------------------------------------------------------
__device__ float g_x [ROWS_ * D_];
__device__ float g_t [ROWS_ * D_];
__device__ __nv_bfloat16 g_ah[ROWS_ * D_];
__device__ __nv_bfloat16 g_al[ROWS_ * D_];
__device__ __nv_bfloat16 g_wth[WT_ELEMS];
__device__ __nv_bfloat16 g_wtl[WT_ELEMS];
__device__ __nv_bfloat16 g_qh[ROWS_ * D_];
__device__ __nv_bfloat16 g_ql[ROWS_ * D_];
__device__ __nv_bfloat16 g_kh[ROWS_ * D_];
__device__ __nv_bfloat16 g_kl[ROWS_ * D_];
__device__ __nv_bfloat16 g_vth[ROWS_ * D_];   // [bh][64][S]
__device__ __nv_bfloat16 g_vtl[ROWS_ * D_];

// ---------------------------------------------------------------------------
// Helpers
// ---------------------------------------------------------------------------
__device__ __forceinline__ uint32_t smem_u32(const void* p) {
    uint32_t a;
    asm("{ .reg .u64 t; cvta.to.shared.u64 t, %1; cvt.u32.u64 %0, t; }"
        : "=r"(a) : "l"(p));
    return a;
}

__device__ __forceinline__ void ldm_x4(uint32_t* r, uint32_t addr) {
    asm("ldmatrix.sync.aligned.m8n8.x4.shared.b16 {%0,%1,%2,%3}, [%4];"
        : "=r"(r[0]), "=r"(r[1]), "=r"(r[2]), "=r"(r[3]) : "r"(addr));
}

__device__ __forceinline__ void mma16816(float* c, const uint32_t* a,
                                         uint32_t b0, uint32_t b1) {
    asm("mma.sync.aligned.m16n8k16.row.col.f32.bf16.bf16.f32 "
        "{%0,%1,%2,%3}, {%4,%5,%6,%7}, {%8,%9}, {%0,%1,%2,%3};"
        : "+f"(c[0]), "+f"(c[1]), "+f"(c[2]), "+f"(c[3])
        : "r"(a[0]), "r"(a[1]), "r"(a[2]), "r"(a[3]), "r"(b0), "r"(b1));
}

__device__ __forceinline__ uint32_t pk_bf16(float lo, float hi) {
    uint32_t r;
    asm("cvt.rn.bf16x2.f32 %0, %1, %2;" : "=r"(r) : "f"(hi), "f"(lo));
    return r;
}

// bare exp2 (no log2e FMUL; operand pre-scaled)
__device__ __forceinline__ float ex2(float x) {
    float r;
    asm("ex2.approx.f32 %0, %1;" : "=f"(r) : "f"(x));
    return r;
}

__device__ __forceinline__ void split2(float c0, float c1, uint32_t& hw, uint32_t& lw) {
    __nv_bfloat16 h0 = __float2bfloat16(c0);
    __nv_bfloat16 h1 = __float2bfloat16(c1);
    __nv_bfloat162 hp; hp.x = h0; hp.y = h1;
    hw = *(uint32_t*)&hp;
    lw = pk_bf16(c0 - __bfloat162float(h0), c1 - __bfloat162float(h1));
}

#define CP_ASYNC16(dst, src) \
    asm volatile("cp.async.cg.shared.global [%0], [%1], 16;" :: "r"(dst), "l"(src))
#define CP_COMMIT() asm volatile("cp.async.commit_group;" ::: "memory")
#define CP_WAIT(n)  asm volatile("cp.async.wait_group %0;" :: "n"(n) : "memory")

// ---------------------------------------------------------------------------
// Unified prep: z<24 layer weight transpose+split; z==24 proj_w; z>=25 gather
// ---------------------------------------------------------------------------
__global__ void prep_all(const float* __restrict__ qw, const float* __restrict__ kw,
                         const float* __restrict__ vw, const float* __restrict__ ow,
                         const float* __restrict__ pw,
                         const int* __restrict__ seq, const float* __restrict__ emb,
                         __nv_bfloat16* __restrict__ th,
                         __nv_bfloat16* __restrict__ tl,
                         __nv_bfloat16* __restrict__ xh,
                         __nv_bfloat16* __restrict__ xl) {
    int z = blockIdx.z;
    if (z >= 25) {
        int tid = threadIdx.y * 32 + threadIdx.x;
        int i = (((z - 25) * 1024 + blockIdx.y * 32 + blockIdx.x) << 8) + tid;
        if (i >= ROWS_ * SEQDIM_ / 2) return;
        int row = i >> 6;
        int c2  = (i & 63) * 2;
        const float* e = emb + seq[row] * SEQDIM_ + c2;
        uint32_t hw, lw;
        split2(e[0], e[1], hw, lw);
        ((uint32_t*)xh)[i] = hw;
        ((uint32_t*)xl)[i] = lw;
        return;
    }
    __shared__ float t[32][33];
    const float* W;
    size_t dof;
    int K;
    if (z < 24) {
        int l = z >> 2, m = z & 3;
        W = (m == 0 ? qw : m == 1 ? kw : m == 2 ? vw : ow) + (size_t)l * D_ * D_;
        dof = WT_PROJ_ELEMS + (size_t)z * WT_MAT_ELEMS;
        K = D_;
    } else {
        if (blockIdx.y >= SEQDIM_ / 32) return;
        W = pw;
        dof = 0;
        K = SEQDIM_;
    }
    int bx = blockIdx.x * 32;
    int by = blockIdx.y * 32;
    #pragma unroll
    for (int i = 0; i < 32; i += 8)
        t[threadIdx.y + i][threadIdx.x] =
            W[(size_t)(by + threadIdx.y + i) * D_ + bx + threadIdx.x];
    __syncthreads();
    #pragma unroll
    for (int i = 0; i < 32; i += 8) {
        float v = t[threadIdx.x][threadIdx.y + i];
        int n = bx + threadIdx.y + i;
        int k = by + threadIdx.x;
        __nv_bfloat16 h = __float2bfloat16(v);
        th[dof + (size_t)n * K + k] = h;
        tl[dof + (size_t)n * K + k] = __float2bfloat16(v - __bfloat162float(h));
    }
}

// ---------------------------------------------------------------------------
// GEMM core (R13 structure)
// ---------------------------------------------------------------------------
#define TILEB  10240
#define CHUNKB (4 * TILEB)
#define GEMM_SMEM (2 * CHUNKB)

template <typename EPI>
__device__ __forceinline__
void gemm_core(const __nv_bfloat16* s0, const __nv_bfloat16* s1,
               const __nv_bfloat16* s2, const __nv_bfloat16* s3,
               int K, char* smem, EPI epilogue) {
    const uint32_t sb = smem_u32(smem);
    const int tid  = threadIdx.x;
    const int lane = tid & 31;
    const int wid  = tid >> 5;
    const int wm = wid & 1;
    const int wn = wid >> 1;

    const int nk = K >> 5;

    auto load_chunk = [&](int c, int stage) {
        const int k0 = c << 5;
        uint32_t buf = sb + stage * CHUNKB;
        #pragma unroll
        for (int i = 0; i < 2; i++) {
            int t = tid + i * 256;
            int row = t >> 2;
            int seg = t & 3;
            uint32_t dst = buf + row * 80 + seg * 16;
            size_t so = (size_t)row * K + k0 + seg * 8;
            CP_ASYNC16(dst,              (const char*)(s0 + so));
            CP_ASYNC16(dst + TILEB,      (const char*)(s1 + so));
            CP_ASYNC16(dst + 2 * TILEB,  (const char*)(s2 + so));
            CP_ASYNC16(dst + 3 * TILEB,  (const char*)(s3 + so));
        }
        CP_COMMIT();
    };

    float acc[4][4][4];
    #pragma unroll
    for (int mi = 0; mi < 4; mi++)
        #pragma unroll
        for (int nb = 0; nb < 4; nb++)
            #pragma unroll
            for (int j = 0; j < 4; j++) acc[mi][nb][j] = 0.f;

    const uint32_t a_off = (uint32_t)((wm * 64 + (lane & 15)) * 80 + (lane >> 4) * 16);
    const uint32_t b_off = (uint32_t)((wn * 32 + ((lane >> 4) & 1) * 8 + (lane & 7)) * 80
                                      + ((lane >> 3) & 1) * 16);

    load_chunk(0, 0);

    for (int c = 0; c < nk; c++) {
        CP_WAIT(0);
        __syncthreads();
        if (c + 1 < nk) load_chunk(c + 1, (c + 1) & 1);

        uint32_t buf = sb + (c & 1) * CHUNKB;
        #pragma unroll
        for (int s = 0; s < 2; s++) {
            uint32_t ah[4][4], al[4][4], wh[2][4], wl[2][4];
            #pragma unroll
            for (int g = 0; g < 4; g++)
                ldm_x4(ah[g], buf + a_off + (uint32_t)(g * 16 * 80 + s * 32));
            #pragma unroll
            for (int h = 0; h < 2; h++)
                ldm_x4(wh[h], buf + 2 * TILEB + b_off + (uint32_t)(h * 16 * 80 + s * 32));
            #pragma unroll
            for (int mi = 0; mi < 4; mi++)
                #pragma unroll
                for (int nb = 0; nb < 4; nb++) {
                    const int h = nb >> 1, j = nb & 1;
                    mma16816(acc[mi][nb], ah[mi], wh[h][2 * j], wh[h][2 * j + 1]);
                }
            #pragma unroll
            for (int h = 0; h < 2; h++)
                ldm_x4(wl[h], buf + 3 * TILEB + b_off + (uint32_t)(h * 16 * 80 + s * 32));
            #pragma unroll
            for (int mi = 0; mi < 4; mi++)
                #pragma unroll
                for (int nb = 0; nb < 4; nb++) {
                    const int h = nb >> 1, j = nb & 1;
                    mma16816(acc[mi][nb], ah[mi], wl[h][2 * j], wl[h][2 * j + 1]);
                }
            #pragma unroll
            for (int g = 0; g < 4; g++)
                ldm_x4(al[g], buf + TILEB + a_off + (uint32_t)(g * 16 * 80 + s * 32));
            #pragma unroll
            for (int mi = 0; mi < 4; mi++)
                #pragma unroll
                for (int nb = 0; nb < 4; nb++) {
                    const int h = nb >> 1, j = nb & 1;
                    mma16816(acc[mi][nb], al[mi], wh[h][2 * j], wh[h][2 * j + 1]);
                }
        }
    }
    __syncthreads();

    epilogue(acc, wm, wn, lane);
}

// ---------------------------------------------------------------------------
// Generic GEMM + bias -> fp32 C (optionally also emit bf16 hi/lo split)
// ---------------------------------------------------------------------------
template <bool SPLIT>
__global__ __launch_bounds__(256, 2)
void gemm_mma(const __nv_bfloat16* __restrict__ Ah,
              const __nv_bfloat16* __restrict__ Al,
              const __nv_bfloat16* __restrict__ Wh,
              const __nv_bfloat16* __restrict__ Wl,
              const float* __restrict__ bias,
              float* __restrict__ C, int N, int K,
              __nv_bfloat16* __restrict__ oh, __nv_bfloat16* __restrict__ ol) {
    extern __shared__ char smem[];
    const int brow = blockIdx.y * 128;
    const int bcol = blockIdx.x * 128;
    gemm_core(Ah + (size_t)brow * K, Al + (size_t)brow * K,
              Wh + (size_t)bcol * K, Wl + (size_t)bcol * K, K, smem,
        [&](float acc[4][4][4], int wm, int wn, int lane) {
            #pragma unroll
            for (int mi = 0; mi < 4; mi++) {
                int row = brow + wm * 64 + mi * 16 + (lane >> 2);
                #pragma unroll
                for (int nb = 0; nb < 4; nb++) {
                    int col = bcol + wn * 32 + nb * 8 + (lane & 3) * 2;
                    float b0 = bias[col], b1 = bias[col + 1];
                    float c00 = acc[mi][nb][0] + b0, c01 = acc[mi][nb][1] + b1;
                    float c10 = acc[mi][nb][2] + b0, c11 = acc[mi][nb][3] + b1;
                    size_t i0 = (size_t)row * N + col;
                    size_t i1 = (size_t)(row + 8) * N + col;
                    *(float2*)(C + i0) = make_float2(c00, c01);
                    *(float2*)(C + i1) = make_float2(c10, c11);
                    if (SPLIT) {
                        uint32_t hw, lw;
                        split2(c00, c01, hw, lw);
                        *(uint32_t*)(oh + i0) = hw; *(uint32_t*)(ol + i0) = lw;
                        split2(c10, c11, hw, lw);
                        *(uint32_t*)(oh + i1) = hw; *(uint32_t*)(ol + i1) = lw;
                    }
                }
            }
        });
}

// ---------------------------------------------------------------------------
// Fused QKV GEMM (N=3072). Q scaled by QSCALE (exp2-domain softmax).
// V emitted transposed+split via smem staging.
// ---------------------------------------------------------------------------
__global__ __launch_bounds__(256, 2)
void gemm_qkv(const __nv_bfloat16* __restrict__ Ah,
              const __nv_bfloat16* __restrict__ Al,
              const __nv_bfloat16* __restrict__ Wh,
              const __nv_bfloat16* __restrict__ Wl,
              const float* __restrict__ qb, const float* __restrict__ kb,
              const float* __restrict__ vb, int lofs,
              __nv_bfloat16* __restrict__ qh, __nv_bfloat16* __restrict__ ql,
              __nv_bfloat16* __restrict__ kh, __nv_bfloat16* __restrict__ kl,
              __nv_bfloat16* __restrict__ vth, __nv_bfloat16* __restrict__ vtl) {
    extern __shared__ char smem[];
    const int K = D_;
    const int brow = blockIdx.y * 128;
    const int bcol = blockIdx.x * 128;
    const int mat = bcol >> 10;
    const int colb = bcol & 1023;
    const float* bias = (mat == 0 ? qb : mat == 1 ? kb : vb) + lofs;
    gemm_core(Ah + (size_t)brow * K, Al + (size_t)brow * K,
              Wh + (size_t)bcol * K, Wl + (size_t)bcol * K, K, smem,
        [&](float acc[4][4][4], int wm, int wn, int lane) {
            if (mat == 2) {
                float* trans = (float*)smem;
                #pragma unroll
                for (int mi = 0; mi < 4; mi++) {
                    int sl = wm * 64 + mi * 16 + (lane >> 2);
                    #pragma unroll
                    for (int nb = 0; nb < 4; nb++) {
                        int dl = wn * 32 + nb * 8 + (lane & 3) * 2;
                        float b0 = bias[colb + dl], b1 = bias[colb + dl + 1];
                        trans[dl * 132 + sl]           = acc[mi][nb][0] + b0;
                        trans[(dl + 1) * 132 + sl]     = acc[mi][nb][1] + b1;
                        trans[dl * 132 + sl + 8]       = acc[mi][nb][2] + b0;
                        trans[(dl + 1) * 132 + sl + 8] = acc[mi][nb][3] + b1;
                    }
                }
                __syncthreads();
                int bb = brow >> 11;
                int s0 = brow & (S_ - 1);
                #pragma unroll
                for (int i = 0; i < 32; i++) {
                    int idx = (int)threadIdx.x + i * 256;
                    int dl = idx >> 6;
                    int sp = idx & 63;
                    float2 v = *(float2*)&trans[dl * 132 + sp * 2];
                    int col = colb + dl;
                    int hh = col >> 6, dd = col & 63;
                    size_t o = ((size_t)(bb * H_ + hh) * HD_ + dd) * S_ + s0 + sp * 2;
                    uint32_t hw, lw;
                    split2(v.x, v.y, hw, lw);
                    *(uint32_t*)(vth + o) = hw;
                    *(uint32_t*)(vtl + o) = lw;
                }
            } else {
                #pragma unroll
                for (int mi = 0; mi < 4; mi++) {
                    int row = brow + wm * 64 + mi * 16 + (lane >> 2);
                    #pragma unroll
                    for (int nb = 0; nb < 4; nb++) {
                        int col = colb + wn * 32 + nb * 8 + (lane & 3) * 2;
                        float b0 = bias[col], b1 = bias[col + 1];
                        float c00 = acc[mi][nb][0] + b0, c01 = acc[mi][nb][1] + b1;
                        float c10 = acc[mi][nb][2] + b0, c11 = acc[mi][nb][3] + b1;
                        size_t i0 = (size_t)row * D_ + col;
                        size_t i1 = (size_t)(row + 8) * D_ + col;
                        __nv_bfloat16* hB = (mat == 0) ? qh : kh;
                        __nv_bfloat16* lB = (mat == 0) ? ql : kl;
                        if (mat == 0) {
                            c00 *= QSCALE; c01 *= QSCALE; c10 *= QSCALE; c11 *= QSCALE;
                        }
                        uint32_t hw, lw;
                        split2(c00, c01, hw, lw);
                        *(uint32_t*)(hB + i0) = hw; *(uint32_t*)(lB + i0) = lw;
                        split2(c10, c11, hw, lw);
                        *(uint32_t*)(hB + i1) = hw; *(uint32_t*)(lB + i1) = lw;
                    }
                }
            }
        });
}

// ---------------------------------------------------------------------------
// Tensor-core flash attention (R14 structure); softmax in exp2 domain.
// 2-stage KV pipeline, single sync/kt, Q-lo in smem, 2 CTAs/SM.
// Output written as bf16 hi/lo split.
// ---------------------------------------------------------------------------
#define AST      36864
#define AKL      9216
#define AMASK    (2 * AST)
#define AQLO     (AMASK + 512)
#define ATT_SMEM (AQLO + 18432)        // 92672

__global__ __launch_bounds__(256, 2)
void attn_mma(const __nv_bfloat16* __restrict__ qh, const __nv_bfloat16* __restrict__ ql,
              const __nv_bfloat16* __restrict__ kh, const __nv_bfloat16* __restrict__ kl,
              const __nv_bfloat16* __restrict__ vth, const __nv_bfloat16* __restrict__ vtl,
              const int* __restrict__ mask,
              __nv_bfloat16* __restrict__ oh, __nv_bfloat16* __restrict__ ol) {
    extern __shared__ char smem[];
    const uint32_t sb = smem_u32(smem);
    const int tid = threadIdx.x, wid = tid >> 5, lane = tid & 31;
    const int q0 = blockIdx.x * 128;
    const int bh = blockIdx.y;
    const int b = bh >> 4, h = bh & 15;
    const size_t rowbase = (size_t)b * S_;

    #pragma unroll
    for (int i = 0; i < 4; i++) {
        int t = tid + i * 256;
        int row = t >> 3, seg = t & 7;
        size_t so = (rowbase + q0 + row) * D_ + h * HD_ + seg * 8;
        CP_ASYNC16(sb + row * 144 + seg * 16,        (const char*)(qh + so));
        CP_ASYNC16(sb + AQLO + row * 144 + seg * 16, (const char*)(ql + so));
    }
    CP_COMMIT(); CP_WAIT(0);
    __syncthreads();

    uint32_t qhf[4][4];
    const uint32_t q_off = (uint32_t)((wid * 16 + (lane & 15)) * 144 + (lane >> 4) * 16);
    #pragma unroll
    for (int s = 0; s < 4; s++)
        ldm_x4(qhf[s], sb + q_off + s * 32);
    __syncthreads();

    auto load_kv = [&](int kt, int st) {
        uint32_t buf = sb + st * AST;
        int key0 = kt * 64;
        #pragma unroll
        for (int i = 0; i < 2; i++) {
            int t = tid + i * 256;
            int row = t >> 3, seg = t & 7;
            uint32_t dst = buf + row * 144 + seg * 16;
            size_t sk = (rowbase + key0 + row) * D_ + h * HD_ + seg * 8;
            CP_ASYNC16(dst,           (const char*)(kh + sk));
            CP_ASYNC16(dst + AKL,     (const char*)(kl + sk));
            size_t sv = ((size_t)bh * HD_ + row) * S_ + key0 + seg * 8;
            CP_ASYNC16(dst + 2 * AKL, (const char*)(vth + sv));
            CP_ASYNC16(dst + 3 * AKL, (const char*)(vtl + sv));
        }
        if (tid < 16)
            CP_ASYNC16(sb + AMASK + st * 256 + tid * 16,
                       (const char*)(mask + b * S_ + key0 + tid * 4));
        CP_COMMIT();
    };

    float oacc[8][4];
    #pragma unroll
    for (int nb = 0; nb < 8; nb++)
        #pragma unroll
        for (int j = 0; j < 4; j++) oacc[nb][j] = 0.f;
    float mrow0 = -1e30f, mrow1 = -1e30f, lrow0 = 0.f, lrow1 = 0.f;

    const uint32_t bfrag_off = (uint32_t)((((lane >> 4) & 1) * 8 + (lane & 7)) * 144
                                          + ((lane >> 3) & 1) * 16);

    const int NKT = S_ / 64;
    load_kv(0, 0);

    for (int kt = 0; kt < NKT; kt++) {
        CP_WAIT(0);
        __syncthreads();
        if (kt + 1 < NKT) load_kv(kt + 1, (kt + 1) & 1);

        uint32_t buf = sb + (kt & 1) * AST;

        float sacc[8][4];
        #pragma unroll
        for (int nb = 0; nb < 8; nb++)
            #pragma unroll
            for (int j = 0; j < 4; j++) sacc[nb][j] = 0.f;

        #pragma unroll
        for (int s = 0; s < 4; s++) {
            uint32_t khf[4][4], klf[4][4], qlf[4];
            #pragma unroll
            for (int g = 0; g < 4; g++)
                ldm_x4(khf[g], buf + bfrag_off + (uint32_t)(g * 16 * 144 + s * 32));
            #pragma unroll
            for (int g = 0; g < 4; g++)
                #pragma unroll
                for (int j = 0; j < 2; j++)
                    mma16816(sacc[g * 2 + j], qhf[s], khf[g][2 * j], khf[g][2 * j + 1]);
            #pragma unroll
            for (int g = 0; g < 4; g++)
                ldm_x4(klf[g], buf + AKL + bfrag_off + (uint32_t)(g * 16 * 144 + s * 32));
            #pragma unroll
            for (int g = 0; g < 4; g++)
                #pragma unroll
                for (int j = 0; j < 2; j++)
                    mma16816(sacc[g * 2 + j], qhf[s], klf[g][2 * j], klf[g][2 * j + 1]);
            ldm_x4(qlf, sb + AQLO + q_off + s * 32);
            #pragma unroll
            for (int g = 0; g < 4; g++)
                #pragma unroll
                for (int j = 0; j < 2; j++)
                    mma16816(sacc[g * 2 + j], qlf, khf[g][2 * j], khf[g][2 * j + 1]);
        }

        {
            const int* smk = (const int*)(smem + AMASK + (kt & 1) * 256);
            int cb = 2 * (lane & 3);
            #pragma unroll
            for (int nb = 0; nb < 8; nb++) {
                if (smk[nb * 8 + cb] == 0)     { sacc[nb][0] = -1e9f; sacc[nb][2] = -1e9f; }
                if (smk[nb * 8 + cb + 1] == 0) { sacc[nb][1] = -1e9f; sacc[nb][3] = -1e9f; }
            }
        }

        float mx0 = -1e30f, mx1 = -1e30f;
        #pragma unroll
        for (int nb = 0; nb < 8; nb++) {
            mx0 = fmaxf(mx0, fmaxf(sacc[nb][0], sacc[nb][1]));
            mx1 = fmaxf(mx1, fmaxf(sacc[nb][2], sacc[nb][3]));
        }
        mx0 = fmaxf(mx0, __shfl_xor_sync(0xffffffffu, mx0, 1));
        mx0 = fmaxf(mx0, __shfl_xor_sync(0xffffffffu, mx0, 2));
        mx1 = fmaxf(mx1, __shfl_xor_sync(0xffffffffu, mx1, 1));
        mx1 = fmaxf(mx1, __shfl_xor_sync(0xffffffffu, mx1, 2));
        float mn0 = fmaxf(mrow0, mx0), mn1 = fmaxf(mrow1, mx1);
        float corr0 = ex2(mrow0 - mn0), corr1 = ex2(mrow1 - mn1);
        float sum0 = 0.f, sum1 = 0.f;
        #pragma unroll
        for (int nb = 0; nb < 8; nb++) {
            sacc[nb][0] = ex2(sacc[nb][0] - mn0);
            sacc[nb][1] = ex2(sacc[nb][1] - mn0);
            sacc[nb][2] = ex2(sacc[nb][2] - mn1);
            sacc[nb][3] = ex2(sacc[nb][3] - mn1);
            sum0 += sacc[nb][0] + sacc[nb][1];
            sum1 += sacc[nb][2] + sacc[nb][3];
        }
        sum0 += __shfl_xor_sync(0xffffffffu, sum0, 1);
        sum0 += __shfl_xor_sync(0xffffffffu, sum0, 2);
        sum1 += __shfl_xor_sync(0xffffffffu, sum1, 1);
        sum1 += __shfl_xor_sync(0xffffffffu, sum1, 2);
        lrow0 = lrow0 * corr0 + sum0;
        lrow1 = lrow1 * corr1 + sum1;
        mrow0 = mn0; mrow1 = mn1;
        #pragma unroll
        for (int nb = 0; nb < 8; nb++) {
            oacc[nb][0] *= corr0; oacc[nb][1] *= corr0;
            oacc[nb][2] *= corr1; oacc[nb][3] *= corr1;
        }

        #pragma unroll
        for (int c = 0; c < 4; c++) {
            uint32_t pha[4], pla[4];
            #pragma unroll
            for (int half = 0; half < 2; half++) {
                int nb = 2 * c + half;
                __nv_bfloat16 b0 = __float2bfloat16(sacc[nb][0]);
                __nv_bfloat16 b1 = __float2bfloat16(sacc[nb][1]);
                __nv_bfloat16 b2 = __float2bfloat16(sacc[nb][2]);
                __nv_bfloat16 b3 = __float2bfloat16(sacc[nb][3]);
                __nv_bfloat162 t01; t01.x = b0; t01.y = b1;
                __nv_bfloat162 t23; t23.x = b2; t23.y = b3;
                pha[half * 2 + 0] = *(uint32_t*)&t01;
                pha[half * 2 + 1] = *(uint32_t*)&t23;
                pla[half * 2 + 0] = pk_bf16(sacc[nb][0] - __bfloat162float(b0),
                                            sacc[nb][1] - __bfloat162float(b1));
                pla[half * 2 + 1] = pk_bf16(sacc[nb][2] - __bfloat162float(b2),
                                            sacc[nb][3] - __bfloat162float(b3));
            }
            uint32_t vhf[4][4], vlf[4][4];
            #pragma unroll
            for (int g = 0; g < 4; g++)
                ldm_x4(vhf[g], buf + 2 * AKL + bfrag_off + (uint32_t)(g * 16 * 144 + c * 32));
            #pragma unroll
            for (int g = 0; g < 4; g++)
                #pragma unroll
                for (int j = 0; j < 2; j++)
                    mma16816(oacc[g * 2 + j], pha, vhf[g][2 * j], vhf[g][2 * j + 1]);
            #pragma unroll
            for (int g = 0; g < 4; g++)
                ldm_x4(vlf[g], buf + 3 * AKL + bfrag_off + (uint32_t)(g * 16 * 144 + c * 32));
            #pragma unroll
            for (int g = 0; g < 4; g++)
                #pragma unroll
                for (int j = 0; j < 2; j++)
                    mma16816(oacc[g * 2 + j], pha, vlf[g][2 * j], vlf[g][2 * j + 1]);
            #pragma unroll
            for (int g = 0; g < 4; g++)
                #pragma unroll
                for (int j = 0; j < 2; j++)
                    mma16816(oacc[g * 2 + j], pla, vhf[g][2 * j], vhf[g][2 * j + 1]);
        }
    }

    float inv0 = 1.0f / lrow0, inv1 = 1.0f / lrow1;
    int r0 = q0 + wid * 16 + (lane >> 2);
    #pragma unroll
    for (int nb = 0; nb < 8; nb++) {
        int col = h * HD_ + nb * 8 + 2 * (lane & 3);
        size_t i0 = (rowbase + r0) * D_ + col;
        size_t i1 = (rowbase + r0 + 8) * D_ + col;
        uint32_t hw, lw;
        split2(oacc[nb][0] * inv0, oacc[nb][1] * inv0, hw, lw);
        *(uint32_t*)(oh + i0) = hw; *(uint32_t*)(ol + i0) = lw;
        split2(oacc[nb][2] * inv1, oacc[nb][3] * inv1, hw, lw);
        *(uint32_t*)(oh + i1) = hw; *(uint32_t*)(ol + i1) = lw;
    }
}

// ---------------------------------------------------------------------------
// Fused residual add + LayerNorm (warp-shuffle reductions)
// ---------------------------------------------------------------------------
template <bool SPLIT>
__global__ __launch_bounds__(256)
void add_ln(const float* __restrict__ x, const float* __restrict__ y,
            const float* __restrict__ g, const float* __restrict__ bta,
            float* __restrict__ out,
            __nv_bfloat16* __restrict__ oh, __nv_bfloat16* __restrict__ ol) {
    __shared__ float red[16];
    int row = blockIdx.x, tid = threadIdx.x;
    int wid = tid >> 5, lane = tid & 31;
    const float* xr = x + (size_t)row * D_;
    const float* yr = y + (size_t)row * D_;

    float v[4];
    float sum = 0.f, sq = 0.f;
    #pragma unroll
    for (int i = 0; i < 4; i++) {
        int c = tid + i * 256;
        v[i] = xr[c] + yr[c];
        sum += v[i];
        sq  += v[i] * v[i];
    }
    #pragma unroll
    for (int off = 16; off; off >>= 1) {
        sum += __shfl_xor_sync(0xffffffffu, sum, off);
        sq  += __shfl_xor_sync(0xffffffffu, sq,  off);
    }
    if (lane == 0) { red[wid] = sum; red[8 + wid] = sq; }
    __syncthreads();
    float ts = red[lane & 7], tq = red[8 + (lane & 7)];
    #pragma unroll
    for (int off = 4; off; off >>= 1) {
        ts += __shfl_xor_sync(0xffffffffu, ts, off);
        tq += __shfl_xor_sync(0xffffffffu, tq, off);
    }
    ts = __shfl_sync(0xffffffffu, ts, 0);
    tq = __shfl_sync(0xffffffffu, tq, 0);
    float mu   = ts * (1.0f / 1024.0f);
    float var  = tq * (1.0f / 1024.0f) - mu * mu;
    float rstd = rsqrtf(var + 1e-5f);

    #pragma unroll
    for (int i = 0; i < 4; i++) {
        int c = tid + i * 256;
        float o = (v[i] - mu) * rstd * g[c] + bta[c];
        out[(size_t)row * D_ + c] = o;
        if (SPLIT) {
            __nv_bfloat16 h = __float2bfloat16(o);
            oh[(size_t)row * D_ + c] = h;
            ol[(size_t)row * D_ + c] = __float2bfloat16(o - __bfloat162float(h));
        }
    }
}

// ---------------------------------------------------------------------------
// Launch
// ---------------------------------------------------------------------------
extern "C" void kernel_launch(void* const* d_in, const int* in_sizes, int n_in,
                              void* d_out, int out_size) {
    const int*   seq    = (const int*)  d_in[0];
    const int*   mask   = (const int*)  d_in[1];
    const float* emb    = (const float*)d_in[2];
    const float* proj_w = (const float*)d_in[3];
    const float* proj_b = (const float*)d_in[4];
    const float* qw     = (const float*)d_in[5];
    const float* qb     = (const float*)d_in[6];
    const float* kw     = (const float*)d_in[7];
    const float* kb     = (const float*)d_in[8];
    const float* vw     = (const float*)d_in[9];
    const float* vb     = (const float*)d_in[10];
    const float* ow     = (const float*)d_in[11];
    const float* ob     = (const float*)d_in[12];
    const float* lng    = (const float*)d_in[13];
    const float* lnb    = (const float*)d_in[14];
    float* out = (float*)d_out;

    float *x, *t;
    __nv_bfloat16 *ah, *al, *wth, *wtl, *qhp, *qlp, *khp, *klp, *vthp, *vtlp;
    cudaGetSymbolAddress((void**)&x,    g_x);
    cudaGetSymbolAddress((void**)&t,    g_t);
    cudaGetSymbolAddress((void**)&ah,   g_ah);
    cudaGetSymbolAddress((void**)&al,   g_al);
    cudaGetSymbolAddress((void**)&wth,  g_wth);
    cudaGetSymbolAddress((void**)&wtl,  g_wtl);
    cudaGetSymbolAddress((void**)&qhp,  g_qh);
    cudaGetSymbolAddress((void**)&qlp,  g_ql);
    cudaGetSymbolAddress((void**)&khp,  g_kh);
    cudaGetSymbolAddress((void**)&klp,  g_kl);
    cudaGetSymbolAddress((void**)&vthp, g_vth);
    cudaGetSymbolAddress((void**)&vtlp, g_vtl);

    cudaFuncSetAttribute(gemm_mma<false>, cudaFuncAttributeMaxDynamicSharedMemorySize, GEMM_SMEM);
    cudaFuncSetAttribute(gemm_mma<true>,  cudaFuncAttributeMaxDynamicSharedMemorySize, GEMM_SMEM);
    cudaFuncSetAttribute(gemm_qkv, cudaFuncAttributeMaxDynamicSharedMemorySize, GEMM_SMEM);
    cudaFuncSetAttribute(attn_mma, cudaFuncAttributeMaxDynamicSharedMemorySize, ATT_SMEM);

    prep_all<<<dim3(D_ / 32, D_ / 32, 27), dim3(32, 8)>>>(qw, kw, vw, ow, proj_w,
                                                          seq, emb, wth, wtl, qhp, qlp);
    dim3 gp(D_ / 128, ROWS_ / 128);
    gemm_mma<true><<<gp, 256, GEMM_SMEM>>>(qhp, qlp, wth, wtl, proj_b, x, D_, SEQDIM_, ah, al);

    dim3 gqkv(3 * D_ / 128, ROWS_ / 128);        // (24, 64)
    dim3 ga(S_ / 128, B_ * H_);                  // (16, 64)
    for (int l = 0; l < L_; l++) {
        size_t off = WT_PROJ_ELEMS + (size_t)(l * 4) * WT_MAT_ELEMS;
        const __nv_bfloat16* owh = wth + off + 3 * WT_MAT_ELEMS;
        const __nv_bfloat16* owl = wtl + off + 3 * WT_MAT_ELEMS;

        gemm_qkv<<<gqkv, 256, GEMM_SMEM>>>(ah, al, wth + off, wtl + off,
                                           qb, kb, vb, l * D_,
                                           qhp, qlp, khp, klp, vthp, vtlp);
        attn_mma<<<ga, 256, ATT_SMEM>>>(qhp, qlp, khp, klp, vthp, vtlp, mask, ah, al);
        gemm_mma<false><<<gp, 256, GEMM_SMEM>>>(ah, al, owh, owl, ob + l * D_, t, D_, D_,
                                                nullptr, nullptr);
        if (l == L_ - 1)
            add_ln<false><<<ROWS_, 256>>>(x, t, lng + l * D_, lnb + l * D_, out, nullptr, nullptr);
        else
            add_ln<true><<<ROWS_, 256>>>(x, t, lng + l * D_, lnb + l * D_, x, ah, al);
    }
}

// round 17
// speedup vs baseline: 1.1682x; 1.1512x over previous
#include <cuda_runtime.h>
#include <cuda_bf16.h>
#include <math.h>
#include <stdint.h>

// Problem constants
#define B_      4
#define S_      2048
#define D_      1024
#define H_      16
#define HD_     64
#define L_      6
#define SEQDIM_ 128
#define ROWS_   (B_ * S_)   // 8192

#define WT_PROJ_ELEMS (D_ * SEQDIM_)
#define WT_MAT_ELEMS  (D_ * D_)
#define WT_ELEMS      (WT_PROJ_ELEMS + 24 * WT_MAT_ELEMS)

// Q pre-scale: 1/sqrt(64) * log2(e)  (softmax runs in exp2 domain)
#define QSCALE  0.18033688f

// ---------------------------------------------------------------------------
// Device scratch
// ---------------------------------------------------------------------------
__device__ float g_x [ROWS_ * D_];
__device__ float g_t [ROWS_ * D_];
__device__ __nv_bfloat16 g_ah[ROWS_ * D_];
__device__ __nv_bfloat16 g_al[ROWS_ * D_];
__device__ __nv_bfloat16 g_wth[WT_ELEMS];
__device__ __nv_bfloat16 g_wtl[WT_ELEMS];
__device__ __nv_bfloat16 g_qh[ROWS_ * D_];
__device__ __nv_bfloat16 g_kh[ROWS_ * D_];
__device__ __nv_bfloat16 g_kl[ROWS_ * D_];
__device__ __nv_bfloat16 g_vth[ROWS_ * D_];   // [bh][64][S]
__device__ __nv_bfloat16 g_vtl[ROWS_ * D_];

// ---------------------------------------------------------------------------
// Helpers
// ---------------------------------------------------------------------------
__device__ __forceinline__ uint32_t smem_u32(const void* p) {
    uint32_t a;
    asm("{ .reg .u64 t; cvta.to.shared.u64 t, %1; cvt.u32.u64 %0, t; }"
        : "=r"(a) : "l"(p));
    return a;
}

__device__ __forceinline__ void ldm_x4(uint32_t* r, uint32_t addr) {
    asm("ldmatrix.sync.aligned.m8n8.x4.shared.b16 {%0,%1,%2,%3}, [%4];"
        : "=r"(r[0]), "=r"(r[1]), "=r"(r[2]), "=r"(r[3]) : "r"(addr));
}

__device__ __forceinline__ void mma16816(float* c, const uint32_t* a,
                                         uint32_t b0, uint32_t b1) {
    asm("mma.sync.aligned.m16n8k16.row.col.f32.bf16.bf16.f32 "
        "{%0,%1,%2,%3}, {%4,%5,%6,%7}, {%8,%9}, {%0,%1,%2,%3};"
        : "+f"(c[0]), "+f"(c[1]), "+f"(c[2]), "+f"(c[3])
        : "r"(a[0]), "r"(a[1]), "r"(a[2]), "r"(a[3]), "r"(b0), "r"(b1));
}

__device__ __forceinline__ uint32_t pk_bf16(float lo, float hi) {
    uint32_t r;
    asm("cvt.rn.bf16x2.f32 %0, %1, %2;" : "=r"(r) : "f"(hi), "f"(lo));
    return r;
}

// bare exp2 (no log2e FMUL; operand pre-scaled)
__device__ __forceinline__ float ex2(float x) {
    float r;
    asm("ex2.approx.f32 %0, %1;" : "=f"(r) : "f"(x));
    return r;
}

__device__ __forceinline__ void split2(float c0, float c1, uint32_t& hw, uint32_t& lw) {
    __nv_bfloat16 h0 = __float2bfloat16(c0);
    __nv_bfloat16 h1 = __float2bfloat16(c1);
    __nv_bfloat162 hp; hp.x = h0; hp.y = h1;
    hw = *(uint32_t*)&hp;
    lw = pk_bf16(c0 - __bfloat162float(h0), c1 - __bfloat162float(h1));
}

#define CP_ASYNC16(dst, src) \
    asm volatile("cp.async.cg.shared.global [%0], [%1], 16;" :: "r"(dst), "l"(src))
#define CP_COMMIT() asm volatile("cp.async.commit_group;" ::: "memory")
#define CP_WAIT(n)  asm volatile("cp.async.wait_group %0;" :: "n"(n) : "memory")

// ---------------------------------------------------------------------------
// Unified prep: z<24 layer weight transpose+split; z==24 proj_w; z>=25 gather
// ---------------------------------------------------------------------------
__global__ void prep_all(const float* __restrict__ qw, const float* __restrict__ kw,
                         const float* __restrict__ vw, const float* __restrict__ ow,
                         const float* __restrict__ pw,
                         const int* __restrict__ seq, const float* __restrict__ emb,
                         __nv_bfloat16* __restrict__ th,
                         __nv_bfloat16* __restrict__ tl,
                         __nv_bfloat16* __restrict__ xh,
                         __nv_bfloat16* __restrict__ xl) {
    int z = blockIdx.z;
    if (z >= 25) {
        int tid = threadIdx.y * 32 + threadIdx.x;
        int i = (((z - 25) * 1024 + blockIdx.y * 32 + blockIdx.x) << 8) + tid;
        if (i >= ROWS_ * SEQDIM_ / 2) return;
        int row = i >> 6;
        int c2  = (i & 63) * 2;
        const float* e = emb + seq[row] * SEQDIM_ + c2;
        uint32_t hw, lw;
        split2(e[0], e[1], hw, lw);
        ((uint32_t*)xh)[i] = hw;
        ((uint32_t*)xl)[i] = lw;
        return;
    }
    __shared__ float t[32][33];
    const float* W;
    size_t dof;
    int K;
    if (z < 24) {
        int l = z >> 2, m = z & 3;
        W = (m == 0 ? qw : m == 1 ? kw : m == 2 ? vw : ow) + (size_t)l * D_ * D_;
        dof = WT_PROJ_ELEMS + (size_t)z * WT_MAT_ELEMS;
        K = D_;
    } else {
        if (blockIdx.y >= SEQDIM_ / 32) return;
        W = pw;
        dof = 0;
        K = SEQDIM_;
    }
    int bx = blockIdx.x * 32;
    int by = blockIdx.y * 32;
    #pragma unroll
    for (int i = 0; i < 32; i += 8)
        t[threadIdx.y + i][threadIdx.x] =
            W[(size_t)(by + threadIdx.y + i) * D_ + bx + threadIdx.x];
    __syncthreads();
    #pragma unroll
    for (int i = 0; i < 32; i += 8) {
        float v = t[threadIdx.x][threadIdx.y + i];
        int n = bx + threadIdx.y + i;
        int k = by + threadIdx.x;
        __nv_bfloat16 h = __float2bfloat16(v);
        th[dof + (size_t)n * K + k] = h;
        tl[dof + (size_t)n * K + k] = __float2bfloat16(v - __bfloat162float(h));
    }
}

// ---------------------------------------------------------------------------
// GEMM core (R13 structure; full 3-pass for projections)
// ---------------------------------------------------------------------------
#define TILEB  10240
#define CHUNKB (4 * TILEB)
#define GEMM_SMEM (2 * CHUNKB)

template <typename EPI>
__device__ __forceinline__
void gemm_core(const __nv_bfloat16* s0, const __nv_bfloat16* s1,
               const __nv_bfloat16* s2, const __nv_bfloat16* s3,
               int K, char* smem, EPI epilogue) {
    const uint32_t sb = smem_u32(smem);
    const int tid  = threadIdx.x;
    const int lane = tid & 31;
    const int wid  = tid >> 5;
    const int wm = wid & 1;
    const int wn = wid >> 1;

    const int nk = K >> 5;

    auto load_chunk = [&](int c, int stage) {
        const int k0 = c << 5;
        uint32_t buf = sb + stage * CHUNKB;
        #pragma unroll
        for (int i = 0; i < 2; i++) {
            int t = tid + i * 256;
            int row = t >> 2;
            int seg = t & 3;
            uint32_t dst = buf + row * 80 + seg * 16;
            size_t so = (size_t)row * K + k0 + seg * 8;
            CP_ASYNC16(dst,              (const char*)(s0 + so));
            CP_ASYNC16(dst + TILEB,      (const char*)(s1 + so));
            CP_ASYNC16(dst + 2 * TILEB,  (const char*)(s2 + so));
            CP_ASYNC16(dst + 3 * TILEB,  (const char*)(s3 + so));
        }
        CP_COMMIT();
    };

    float acc[4][4][4];
    #pragma unroll
    for (int mi = 0; mi < 4; mi++)
        #pragma unroll
        for (int nb = 0; nb < 4; nb++)
            #pragma unroll
            for (int j = 0; j < 4; j++) acc[mi][nb][j] = 0.f;

    const uint32_t a_off = (uint32_t)((wm * 64 + (lane & 15)) * 80 + (lane >> 4) * 16);
    const uint32_t b_off = (uint32_t)((wn * 32 + ((lane >> 4) & 1) * 8 + (lane & 7)) * 80
                                      + ((lane >> 3) & 1) * 16);

    load_chunk(0, 0);

    for (int c = 0; c < nk; c++) {
        CP_WAIT(0);
        __syncthreads();
        if (c + 1 < nk) load_chunk(c + 1, (c + 1) & 1);

        uint32_t buf = sb + (c & 1) * CHUNKB;
        #pragma unroll
        for (int s = 0; s < 2; s++) {
            uint32_t ah[4][4], al[4][4], wh[2][4], wl[2][4];
            #pragma unroll
            for (int g = 0; g < 4; g++)
                ldm_x4(ah[g], buf + a_off + (uint32_t)(g * 16 * 80 + s * 32));
            #pragma unroll
            for (int h = 0; h < 2; h++)
                ldm_x4(wh[h], buf + 2 * TILEB + b_off + (uint32_t)(h * 16 * 80 + s * 32));
            #pragma unroll
            for (int mi = 0; mi < 4; mi++)
                #pragma unroll
                for (int nb = 0; nb < 4; nb++) {
                    const int h = nb >> 1, j = nb & 1;
                    mma16816(acc[mi][nb], ah[mi], wh[h][2 * j], wh[h][2 * j + 1]);
                }
            #pragma unroll
            for (int h = 0; h < 2; h++)
                ldm_x4(wl[h], buf + 3 * TILEB + b_off + (uint32_t)(h * 16 * 80 + s * 32));
            #pragma unroll
            for (int mi = 0; mi < 4; mi++)
                #pragma unroll
                for (int nb = 0; nb < 4; nb++) {
                    const int h = nb >> 1, j = nb & 1;
                    mma16816(acc[mi][nb], ah[mi], wl[h][2 * j], wl[h][2 * j + 1]);
                }
            #pragma unroll
            for (int g = 0; g < 4; g++)
                ldm_x4(al[g], buf + TILEB + a_off + (uint32_t)(g * 16 * 80 + s * 32));
            #pragma unroll
            for (int mi = 0; mi < 4; mi++)
                #pragma unroll
                for (int nb = 0; nb < 4; nb++) {
                    const int h = nb >> 1, j = nb & 1;
                    mma16816(acc[mi][nb], al[mi], wh[h][2 * j], wh[h][2 * j + 1]);
                }
        }
    }
    __syncthreads();

    epilogue(acc, wm, wn, lane);
}

// ---------------------------------------------------------------------------
// Generic GEMM + bias -> fp32 C (optionally also emit bf16 hi/lo split)
// ---------------------------------------------------------------------------
template <bool SPLIT>
__global__ __launch_bounds__(256, 2)
void gemm_mma(const __nv_bfloat16* __restrict__ Ah,
              const __nv_bfloat16* __restrict__ Al,
              const __nv_bfloat16* __restrict__ Wh,
              const __nv_bfloat16* __restrict__ Wl,
              const float* __restrict__ bias,
              float* __restrict__ C, int N, int K,
              __nv_bfloat16* __restrict__ oh, __nv_bfloat16* __restrict__ ol) {
    extern __shared__ char smem[];
    const int brow = blockIdx.y * 128;
    const int bcol = blockIdx.x * 128;
    gemm_core(Ah + (size_t)brow * K, Al + (size_t)brow * K,
              Wh + (size_t)bcol * K, Wl + (size_t)bcol * K, K, smem,
        [&](float acc[4][4][4], int wm, int wn, int lane) {
            #pragma unroll
            for (int mi = 0; mi < 4; mi++) {
                int row = brow + wm * 64 + mi * 16 + (lane >> 2);
                #pragma unroll
                for (int nb = 0; nb < 4; nb++) {
                    int col = bcol + wn * 32 + nb * 8 + (lane & 3) * 2;
                    float b0 = bias[col], b1 = bias[col + 1];
                    float c00 = acc[mi][nb][0] + b0, c01 = acc[mi][nb][1] + b1;
                    float c10 = acc[mi][nb][2] + b0, c11 = acc[mi][nb][3] + b1;
                    size_t i0 = (size_t)row * N + col;
                    size_t i1 = (size_t)(row + 8) * N + col;
                    *(float2*)(C + i0) = make_float2(c00, c01);
                    *(float2*)(C + i1) = make_float2(c10, c11);
                    if (SPLIT) {
                        uint32_t hw, lw;
                        split2(c00, c01, hw, lw);
                        *(uint32_t*)(oh + i0) = hw; *(uint32_t*)(ol + i0) = lw;
                        split2(c10, c11, hw, lw);
                        *(uint32_t*)(oh + i1) = hw; *(uint32_t*)(ol + i1) = lw;
                    }
                }
            }
        });
}

// ---------------------------------------------------------------------------
// Fused QKV GEMM (N=3072). Q: hi-only bf16, scaled by QSCALE.
// K: hi/lo split. V: transposed+split via smem staging.
// ---------------------------------------------------------------------------
__global__ __launch_bounds__(256, 2)
void gemm_qkv(const __nv_bfloat16* __restrict__ Ah,
              const __nv_bfloat16* __restrict__ Al,
              const __nv_bfloat16* __restrict__ Wh,
              const __nv_bfloat16* __restrict__ Wl,
              const float* __restrict__ qb, const float* __restrict__ kb,
              const float* __restrict__ vb, int lofs,
              __nv_bfloat16* __restrict__ qh,
              __nv_bfloat16* __restrict__ kh, __nv_bfloat16* __restrict__ kl,
              __nv_bfloat16* __restrict__ vth, __nv_bfloat16* __restrict__ vtl) {
    extern __shared__ char smem[];
    const int K = D_;
    const int brow = blockIdx.y * 128;
    const int bcol = blockIdx.x * 128;
    const int mat = bcol >> 10;
    const int colb = bcol & 1023;
    const float* bias = (mat == 0 ? qb : mat == 1 ? kb : vb) + lofs;
    gemm_core(Ah + (size_t)brow * K, Al + (size_t)brow * K,
              Wh + (size_t)bcol * K, Wl + (size_t)bcol * K, K, smem,
        [&](float acc[4][4][4], int wm, int wn, int lane) {
            if (mat == 2) {
                float* trans = (float*)smem;
                #pragma unroll
                for (int mi = 0; mi < 4; mi++) {
                    int sl = wm * 64 + mi * 16 + (lane >> 2);
                    #pragma unroll
                    for (int nb = 0; nb < 4; nb++) {
                        int dl = wn * 32 + nb * 8 + (lane & 3) * 2;
                        float b0 = bias[colb + dl], b1 = bias[colb + dl + 1];
                        trans[dl * 132 + sl]           = acc[mi][nb][0] + b0;
                        trans[(dl + 1) * 132 + sl]     = acc[mi][nb][1] + b1;
                        trans[dl * 132 + sl + 8]       = acc[mi][nb][2] + b0;
                        trans[(dl + 1) * 132 + sl + 8] = acc[mi][nb][3] + b1;
                    }
                }
                __syncthreads();
                int bb = brow >> 11;
                int s0 = brow & (S_ - 1);
                #pragma unroll
                for (int i = 0; i < 32; i++) {
                    int idx = (int)threadIdx.x + i * 256;
                    int dl = idx >> 6;
                    int sp = idx & 63;
                    float2 v = *(float2*)&trans[dl * 132 + sp * 2];
                    int col = colb + dl;
                    int hh = col >> 6, dd = col & 63;
                    size_t o = ((size_t)(bb * H_ + hh) * HD_ + dd) * S_ + s0 + sp * 2;
                    uint32_t hw, lw;
                    split2(v.x, v.y, hw, lw);
                    *(uint32_t*)(vth + o) = hw;
                    *(uint32_t*)(vtl + o) = lw;
                }
            } else if (mat == 0) {
                // Q: hi-only bf16, exp2-domain scale
                #pragma unroll
                for (int mi = 0; mi < 4; mi++) {
                    int row = brow + wm * 64 + mi * 16 + (lane >> 2);
                    #pragma unroll
                    for (int nb = 0; nb < 4; nb++) {
                        int col = colb + wn * 32 + nb * 8 + (lane & 3) * 2;
                        float b0 = bias[col], b1 = bias[col + 1];
                        float c00 = (acc[mi][nb][0] + b0) * QSCALE;
                        float c01 = (acc[mi][nb][1] + b1) * QSCALE;
                        float c10 = (acc[mi][nb][2] + b0) * QSCALE;
                        float c11 = (acc[mi][nb][3] + b1) * QSCALE;
                        size_t i0 = (size_t)row * D_ + col;
                        size_t i1 = (size_t)(row + 8) * D_ + col;
                        *(uint32_t*)(qh + i0) = pk_bf16(c00, c01);
                        *(uint32_t*)(qh + i1) = pk_bf16(c10, c11);
                    }
                }
            } else {
                // K: hi/lo split
                #pragma unroll
                for (int mi = 0; mi < 4; mi++) {
                    int row = brow + wm * 64 + mi * 16 + (lane >> 2);
                    #pragma unroll
                    for (int nb = 0; nb < 4; nb++) {
                        int col = colb + wn * 32 + nb * 8 + (lane & 3) * 2;
                        float b0 = bias[col], b1 = bias[col + 1];
                        float c00 = acc[mi][nb][0] + b0, c01 = acc[mi][nb][1] + b1;
                        float c10 = acc[mi][nb][2] + b0, c11 = acc[mi][nb][3] + b1;
                        size_t i0 = (size_t)row * D_ + col;
                        size_t i1 = (size_t)(row + 8) * D_ + col;
                        uint32_t hw, lw;
                        split2(c00, c01, hw, lw);
                        *(uint32_t*)(kh + i0) = hw; *(uint32_t*)(kl + i0) = lw;
                        split2(c10, c11, hw, lw);
                        *(uint32_t*)(kh + i1) = hw; *(uint32_t*)(kl + i1) = lw;
                    }
                }
            }
        });
}

// ---------------------------------------------------------------------------
// Tensor-core flash attention; exp2-domain softmax. 2-pass QK (QhKh + QhKl),
// 2-pass PV (PhVh + PhVl). 2-stage KV pipeline, single sync/kt, 2 CTAs/SM.
// Output written as bf16 hi/lo split.
// ---------------------------------------------------------------------------
#define AST      36864
#define AKL      9216
#define AMASK    (2 * AST)
#define ATT_SMEM (AMASK + 512)         // 74240

__global__ __launch_bounds__(256, 2)
void attn_mma(const __nv_bfloat16* __restrict__ qh,
              const __nv_bfloat16* __restrict__ kh, const __nv_bfloat16* __restrict__ kl,
              const __nv_bfloat16* __restrict__ vth, const __nv_bfloat16* __restrict__ vtl,
              const int* __restrict__ mask,
              __nv_bfloat16* __restrict__ oh, __nv_bfloat16* __restrict__ ol) {
    extern __shared__ char smem[];
    const uint32_t sb = smem_u32(smem);
    const int tid = threadIdx.x, wid = tid >> 5, lane = tid & 31;
    const int q0 = blockIdx.x * 128;
    const int bh = blockIdx.y;
    const int b = bh >> 4, h = bh & 15;
    const size_t rowbase = (size_t)b * S_;

    // Q-hi staged in stage-0 area (consumed to regs)
    #pragma unroll
    for (int i = 0; i < 4; i++) {
        int t = tid + i * 256;
        int row = t >> 3, seg = t & 7;
        size_t so = (rowbase + q0 + row) * D_ + h * HD_ + seg * 8;
        CP_ASYNC16(sb + row * 144 + seg * 16, (const char*)(qh + so));
    }
    CP_COMMIT(); CP_WAIT(0);
    __syncthreads();

    uint32_t qhf[4][4];
    const uint32_t q_off = (uint32_t)((wid * 16 + (lane & 15)) * 144 + (lane >> 4) * 16);
    #pragma unroll
    for (int s = 0; s < 4; s++)
        ldm_x4(qhf[s], sb + q_off + s * 32);
    __syncthreads();

    auto load_kv = [&](int kt, int st) {
        uint32_t buf = sb + st * AST;
        int key0 = kt * 64;
        #pragma unroll
        for (int i = 0; i < 2; i++) {
            int t = tid + i * 256;
            int row = t >> 3, seg = t & 7;
            uint32_t dst = buf + row * 144 + seg * 16;
            size_t sk = (rowbase + key0 + row) * D_ + h * HD_ + seg * 8;
            CP_ASYNC16(dst,           (const char*)(kh + sk));
            CP_ASYNC16(dst + AKL,     (const char*)(kl + sk));
            size_t sv = ((size_t)bh * HD_ + row) * S_ + key0 + seg * 8;
            CP_ASYNC16(dst + 2 * AKL, (const char*)(vth + sv));
            CP_ASYNC16(dst + 3 * AKL, (const char*)(vtl + sv));
        }
        if (tid < 16)
            CP_ASYNC16(sb + AMASK + st * 256 + tid * 16,
                       (const char*)(mask + b * S_ + key0 + tid * 4));
        CP_COMMIT();
    };

    float oacc[8][4];
    #pragma unroll
    for (int nb = 0; nb < 8; nb++)
        #pragma unroll
        for (int j = 0; j < 4; j++) oacc[nb][j] = 0.f;
    float mrow0 = -1e30f, mrow1 = -1e30f, lrow0 = 0.f, lrow1 = 0.f;

    const uint32_t bfrag_off = (uint32_t)((((lane >> 4) & 1) * 8 + (lane & 7)) * 144
                                          + ((lane >> 3) & 1) * 16);

    const int NKT = S_ / 64;
    load_kv(0, 0);

    for (int kt = 0; kt < NKT; kt++) {
        CP_WAIT(0);
        __syncthreads();
        if (kt + 1 < NKT) load_kv(kt + 1, (kt + 1) & 1);

        uint32_t buf = sb + (kt & 1) * AST;

        float sacc[8][4];
        #pragma unroll
        for (int nb = 0; nb < 8; nb++)
            #pragma unroll
            for (int j = 0; j < 4; j++) sacc[nb][j] = 0.f;

        // S = Qh*(Kh+Kl)  (2-pass)
        #pragma unroll
        for (int s = 0; s < 4; s++) {
            uint32_t khf[4][4], klf[4][4];
            #pragma unroll
            for (int g = 0; g < 4; g++)
                ldm_x4(khf[g], buf + bfrag_off + (uint32_t)(g * 16 * 144 + s * 32));
            #pragma unroll
            for (int g = 0; g < 4; g++)
                #pragma unroll
                for (int j = 0; j < 2; j++)
                    mma16816(sacc[g * 2 + j], qhf[s], khf[g][2 * j], khf[g][2 * j + 1]);
            #pragma unroll
            for (int g = 0; g < 4; g++)
                ldm_x4(klf[g], buf + AKL + bfrag_off + (uint32_t)(g * 16 * 144 + s * 32));
            #pragma unroll
            for (int g = 0; g < 4; g++)
                #pragma unroll
                for (int j = 0; j < 2; j++)
                    mma16816(sacc[g * 2 + j], qhf[s], klf[g][2 * j], klf[g][2 * j + 1]);
        }

        {
            const int* smk = (const int*)(smem + AMASK + (kt & 1) * 256);
            int cb = 2 * (lane & 3);
            #pragma unroll
            for (int nb = 0; nb < 8; nb++) {
                if (smk[nb * 8 + cb] == 0)     { sacc[nb][0] = -1e9f; sacc[nb][2] = -1e9f; }
                if (smk[nb * 8 + cb + 1] == 0) { sacc[nb][1] = -1e9f; sacc[nb][3] = -1e9f; }
            }
        }

        float mx0 = -1e30f, mx1 = -1e30f;
        #pragma unroll
        for (int nb = 0; nb < 8; nb++) {
            mx0 = fmaxf(mx0, fmaxf(sacc[nb][0], sacc[nb][1]));
            mx1 = fmaxf(mx1, fmaxf(sacc[nb][2], sacc[nb][3]));
        }
        mx0 = fmaxf(mx0, __shfl_xor_sync(0xffffffffu, mx0, 1));
        mx0 = fmaxf(mx0, __shfl_xor_sync(0xffffffffu, mx0, 2));
        mx1 = fmaxf(mx1, __shfl_xor_sync(0xffffffffu, mx1, 1));
        mx1 = fmaxf(mx1, __shfl_xor_sync(0xffffffffu, mx1, 2));
        float mn0 = fmaxf(mrow0, mx0), mn1 = fmaxf(mrow1, mx1);
        float corr0 = ex2(mrow0 - mn0), corr1 = ex2(mrow1 - mn1);
        float sum0 = 0.f, sum1 = 0.f;
        #pragma unroll
        for (int nb = 0; nb < 8; nb++) {
            sacc[nb][0] = ex2(sacc[nb][0] - mn0);
            sacc[nb][1] = ex2(sacc[nb][1] - mn0);
            sacc[nb][2] = ex2(sacc[nb][2] - mn1);
            sacc[nb][3] = ex2(sacc[nb][3] - mn1);
            sum0 += sacc[nb][0] + sacc[nb][1];
            sum1 += sacc[nb][2] + sacc[nb][3];
        }
        sum0 += __shfl_xor_sync(0xffffffffu, sum0, 1);
        sum0 += __shfl_xor_sync(0xffffffffu, sum0, 2);
        sum1 += __shfl_xor_sync(0xffffffffu, sum1, 1);
        sum1 += __shfl_xor_sync(0xffffffffu, sum1, 2);
        lrow0 = lrow0 * corr0 + sum0;
        lrow1 = lrow1 * corr1 + sum1;
        mrow0 = mn0; mrow1 = mn1;
        #pragma unroll
        for (int nb = 0; nb < 8; nb++) {
            oacc[nb][0] *= corr0; oacc[nb][1] *= corr0;
            oacc[nb][2] *= corr1; oacc[nb][3] *= corr1;
        }

        // O += Ph*(Vh+Vl)  (2-pass; P cast to bf16)
        #pragma unroll
        for (int c = 0; c < 4; c++) {
            uint32_t pha[4];
            #pragma unroll
            for (int half = 0; half < 2; half++) {
                int nb = 2 * c + half;
                pha[half * 2 + 0] = pk_bf16(sacc[nb][0], sacc[nb][1]);
                pha[half * 2 + 1] = pk_bf16(sacc[nb][2], sacc[nb][3]);
            }
            uint32_t vhf[4][4], vlf[4][4];
            #pragma unroll
            for (int g = 0; g < 4; g++)
                ldm_x4(vhf[g], buf + 2 * AKL + bfrag_off + (uint32_t)(g * 16 * 144 + c * 32));
            #pragma unroll
            for (int g = 0; g < 4; g++)
                #pragma unroll
                for (int j = 0; j < 2; j++)
                    mma16816(oacc[g * 2 + j], pha, vhf[g][2 * j], vhf[g][2 * j + 1]);
            #pragma unroll
            for (int g = 0; g < 4; g++)
                ldm_x4(vlf[g], buf + 3 * AKL + bfrag_off + (uint32_t)(g * 16 * 144 + c * 32));
            #pragma unroll
            for (int g = 0; g < 4; g++)
                #pragma unroll
                for (int j = 0; j < 2; j++)
                    mma16816(oacc[g * 2 + j], pha, vlf[g][2 * j], vlf[g][2 * j + 1]);
        }
    }

    float inv0 = 1.0f / lrow0, inv1 = 1.0f / lrow1;
    int r0 = q0 + wid * 16 + (lane >> 2);
    #pragma unroll
    for (int nb = 0; nb < 8; nb++) {
        int col = h * HD_ + nb * 8 + 2 * (lane & 3);
        size_t i0 = (rowbase + r0) * D_ + col;
        size_t i1 = (rowbase + r0 + 8) * D_ + col;
        uint32_t hw, lw;
        split2(oacc[nb][0] * inv0, oacc[nb][1] * inv0, hw, lw);
        *(uint32_t*)(oh + i0) = hw; *(uint32_t*)(ol + i0) = lw;
        split2(oacc[nb][2] * inv1, oacc[nb][3] * inv1, hw, lw);
        *(uint32_t*)(oh + i1) = hw; *(uint32_t*)(ol + i1) = lw;
    }
}

// ---------------------------------------------------------------------------
// Fused residual add + LayerNorm (warp-shuffle reductions)
// ---------------------------------------------------------------------------
template <bool SPLIT>
__global__ __launch_bounds__(256)
void add_ln(const float* __restrict__ x, const float* __restrict__ y,
            const float* __restrict__ g, const float* __restrict__ bta,
            float* __restrict__ out,
            __nv_bfloat16* __restrict__ oh, __nv_bfloat16* __restrict__ ol) {
    __shared__ float red[16];
    int row = blockIdx.x, tid = threadIdx.x;
    int wid = tid >> 5, lane = tid & 31;
    const float* xr = x + (size_t)row * D_;
    const float* yr = y + (size_t)row * D_;

    float v[4];
    float sum = 0.f, sq = 0.f;
    #pragma unroll
    for (int i = 0; i < 4; i++) {
        int c = tid + i * 256;
        v[i] = xr[c] + yr[c];
        sum += v[i];
        sq  += v[i] * v[i];
    }
    #pragma unroll
    for (int off = 16; off; off >>= 1) {
        sum += __shfl_xor_sync(0xffffffffu, sum, off);
        sq  += __shfl_xor_sync(0xffffffffu, sq,  off);
    }
    if (lane == 0) { red[wid] = sum; red[8 + wid] = sq; }
    __syncthreads();
    float ts = red[lane & 7], tq = red[8 + (lane & 7)];
    #pragma unroll
    for (int off = 4; off; off >>= 1) {
        ts += __shfl_xor_sync(0xffffffffu, ts, off);
        tq += __shfl_xor_sync(0xffffffffu, tq, off);
    }
    ts = __shfl_sync(0xffffffffu, ts, 0);
    tq = __shfl_sync(0xffffffffu, tq, 0);
    float mu   = ts * (1.0f / 1024.0f);
    float var  = tq * (1.0f / 1024.0f) - mu * mu;
    float rstd = rsqrtf(var + 1e-5f);

    #pragma unroll
    for (int i = 0; i < 4; i++) {
        int c = tid + i * 256;
        float o = (v[i] - mu) * rstd * g[c] + bta[c];
        out[(size_t)row * D_ + c] = o;
        if (SPLIT) {
            __nv_bfloat16 h = __float2bfloat16(o);
            oh[(size_t)row * D_ + c] = h;
            ol[(size_t)row * D_ + c] = __float2bfloat16(o - __bfloat162float(h));
        }
    }
}

// ---------------------------------------------------------------------------
// Launch
// ---------------------------------------------------------------------------
extern "C" void kernel_launch(void* const* d_in, const int* in_sizes, int n_in,
                              void* d_out, int out_size) {
    const int*   seq    = (const int*)  d_in[0];
    const int*   mask   = (const int*)  d_in[1];
    const float* emb    = (const float*)d_in[2];
    const float* proj_w = (const float*)d_in[3];
    const float* proj_b = (const float*)d_in[4];
    const float* qw     = (const float*)d_in[5];
    const float* qb     = (const float*)d_in[6];
    const float* kw     = (const float*)d_in[7];
    const float* kb     = (const float*)d_in[8];
    const float* vw     = (const float*)d_in[9];
    const float* vb     = (const float*)d_in[10];
    const float* ow     = (const float*)d_in[11];
    const float* ob     = (const float*)d_in[12];
    const float* lng    = (const float*)d_in[13];
    const float* lnb    = (const float*)d_in[14];
    float* out = (float*)d_out;

    float *x, *t;
    __nv_bfloat16 *ah, *al, *wth, *wtl, *qhp, *khp, *klp, *vthp, *vtlp;
    cudaGetSymbolAddress((void**)&x,    g_x);
    cudaGetSymbolAddress((void**)&t,    g_t);
    cudaGetSymbolAddress((void**)&ah,   g_ah);
    cudaGetSymbolAddress((void**)&al,   g_al);
    cudaGetSymbolAddress((void**)&wth,  g_wth);
    cudaGetSymbolAddress((void**)&wtl,  g_wtl);
    cudaGetSymbolAddress((void**)&qhp,  g_qh);
    cudaGetSymbolAddress((void**)&khp,  g_kh);
    cudaGetSymbolAddress((void**)&klp,  g_kl);
    cudaGetSymbolAddress((void**)&vthp, g_vth);
    cudaGetSymbolAddress((void**)&vtlp, g_vtl);

    cudaFuncSetAttribute(gemm_mma<false>, cudaFuncAttributeMaxDynamicSharedMemorySize, GEMM_SMEM);
    cudaFuncSetAttribute(gemm_mma<true>,  cudaFuncAttributeMaxDynamicSharedMemorySize, GEMM_SMEM);
    cudaFuncSetAttribute(gemm_qkv, cudaFuncAttributeMaxDynamicSharedMemorySize, GEMM_SMEM);
    cudaFuncSetAttribute(attn_mma, cudaFuncAttributeMaxDynamicSharedMemorySize, ATT_SMEM);

    // embedding split staged in g_kh/g_kl scratch
    prep_all<<<dim3(D_ / 32, D_ / 32, 27), dim3(32, 8)>>>(qw, kw, vw, ow, proj_w,
                                                          seq, emb, wth, wtl, khp, klp);
    dim3 gp(D_ / 128, ROWS_ / 128);
    gemm_mma<true><<<gp, 256, GEMM_SMEM>>>(khp, klp, wth, wtl, proj_b, x, D_, SEQDIM_, ah, al);

    dim3 gqkv(3 * D_ / 128, ROWS_ / 128);        // (24, 64)
    dim3 ga(S_ / 128, B_ * H_);                  // (16, 64)
    for (int l = 0; l < L_; l++) {
        size_t off = WT_PROJ_ELEMS + (size_t)(l * 4) * WT_MAT_ELEMS;
        const __nv_bfloat16* owh = wth + off + 3 * WT_MAT_ELEMS;
        const __nv_bfloat16* owl = wtl + off + 3 * WT_MAT_ELEMS;

        gemm_qkv<<<gqkv, 256, GEMM_SMEM>>>(ah, al, wth + off, wtl + off,
                                           qb, kb, vb, l * D_,
                                           qhp, khp, klp, vthp, vtlp);
        attn_mma<<<ga, 256, ATT_SMEM>>>(qhp, khp, klp, vthp, vtlp, mask, ah, al);
        gemm_mma<false><<<gp, 256, GEMM_SMEM>>>(ah, al, owh, owl, ob + l * D_, t, D_, D_,
                                                nullptr, nullptr);
        if (l == L_ - 1)
            add_ln<false><<<ROWS_, 256>>>(x, t, lng + l * D_, lnb + l * D_, out, nullptr, nullptr);
        else
            add_ln<true><<<ROWS_, 256>>>(x, t, lng + l * D_, lnb + l * D_, x, ah, al);
    }
}